// round 11
// baseline (speedup 1.0000x reference)
#include <cuda_runtime.h>
#include <cuda_bf16.h>
#include <cstdint>

#define BBAT 4
#define TT 2048
#define DM 2048
#define NH 16
#define DH 128
#define MROWS (BBAT * TT)

// ---- scratch ----
__device__ __nv_bfloat16 g_xhi[(size_t)MROWS * DM], g_xlo[(size_t)MROWS * DM];
__device__ __nv_bfloat16 g_chi[(size_t)MROWS * DM], g_clo[(size_t)MROWS * DM];
__device__ __nv_bfloat16 g_qhi[(size_t)MROWS * DM], g_qlo[(size_t)MROWS * DM];
__device__ __nv_bfloat16 g_khi[(size_t)MROWS * DH], g_klo[(size_t)MROWS * DH];
__device__ __nv_bfloat16 g_vthi[(size_t)DH * MROWS], g_vtlo[(size_t)DH * MROWS];
__device__ __nv_bfloat16 g_wqhi[(size_t)DM * DM], g_wqlo[(size_t)DM * DM];
__device__ __nv_bfloat16 g_wkhi[(size_t)DH * DM], g_wklo[(size_t)DH * DM];
__device__ __nv_bfloat16 g_wvhi[(size_t)DH * DM], g_wvlo[(size_t)DH * DM];
__device__ __nv_bfloat16 g_wohi[(size_t)DM * DM], g_wolo[(size_t)DM * DM];

// ---- PTX helpers ----
__device__ __forceinline__ uint32_t smem_u32(const void* p) {
    uint32_t a;
    asm("{ .reg .u64 t; cvta.to.shared.u64 t, %1; cvt.u32.u64 %0, t; }" : "=r"(a) : "l"(p));
    return a;
}
#define CP16(s, g) \
    asm volatile("cp.async.cg.shared.global [%0], [%1], 16;" :: "r"(s), "l"(g))
#define CP_COMMIT() asm volatile("cp.async.commit_group;" ::: "memory")
#define CP_WAIT1() asm volatile("cp.async.wait_group 1;" ::: "memory")
#define CP_WAIT0() asm volatile("cp.async.wait_group 0;" ::: "memory")

__device__ __forceinline__ void ldsm_x4(uint32_t& r0, uint32_t& r1, uint32_t& r2,
                                        uint32_t& r3, uint32_t addr) {
    asm volatile("ldmatrix.sync.aligned.m8n8.x4.shared.b16 {%0,%1,%2,%3}, [%4];"
                 : "=r"(r0), "=r"(r1), "=r"(r2), "=r"(r3) : "r"(addr));
}
__device__ __forceinline__ void mma16816(float* c, const uint32_t* a, const uint32_t* b) {
    asm volatile("mma.sync.aligned.m16n8k16.row.col.f32.bf16.bf16.f32 "
                 "{%0,%1,%2,%3}, {%4,%5,%6,%7}, {%8,%9}, {%0,%1,%2,%3};"
                 : "+f"(c[0]), "+f"(c[1]), "+f"(c[2]), "+f"(c[3])
                 : "r"(a[0]), "r"(a[1]), "r"(a[2]), "r"(a[3]), "r"(b[0]), "r"(b[1]));
}
__device__ __forceinline__ float ex2f(float x) {
    float y;
    asm("ex2.approx.f32 %0, %1;" : "=f"(y) : "f"(x));
    return y;
}

// ---- fp32 -> bf16 hi/lo ----
__device__ __forceinline__ void split1(float v, __nv_bfloat16& h, __nv_bfloat16& l) {
    h = __float2bfloat16(v);
    l = __float2bfloat16(v - __bfloat162float(h));
}
__device__ __forceinline__ uint32_t pk2(__nv_bfloat16 a, __nv_bfloat16 b) {
    return (uint32_t)__bfloat16_as_ushort(a) | ((uint32_t)__bfloat16_as_ushort(b) << 16);
}
__device__ __forceinline__ uint32_t splitpk_hi(float a, float b) {
    return pk2(__float2bfloat16(a), __float2bfloat16(b));
}
__device__ __forceinline__ uint32_t splitpk_lo(float a, float b) {
    __nv_bfloat16 ha = __float2bfloat16(a), hb = __float2bfloat16(b);
    return pk2(__float2bfloat16(a - __bfloat162float(ha)),
               __float2bfloat16(b - __bfloat162float(hb)));
}

// ============================================================
// Fused prep (unchanged, validated)
// ============================================================
__device__ __forceinline__ void do_tsplit(const float* __restrict__ W,
                                          __nv_bfloat16* hi, __nv_bfloat16* lo,
                                          int Kd, int Nd, int bx2,
                                          float (*t)[33]) {
    const int xw = Nd / 32;
    const int nb = (bx2 % xw) * 32, kb = (bx2 / xw) * 32;
    const int tx = threadIdx.x & 31, ty = threadIdx.x >> 5;
#pragma unroll
    for (int i = 0; i < 4; i++)
        t[ty + 8 * i][tx] = W[(size_t)(kb + ty + 8 * i) * Nd + nb + tx];
    __syncthreads();
#pragma unroll
    for (int i = 0; i < 4; i++) {
        const int nrow = ty + 8 * i;
        __nv_bfloat16 h, l;
        split1(t[tx][nrow], h, l);
        const size_t o = (size_t)(nb + nrow) * Kd + kb + tx;
        hi[o] = h; lo[o] = l;
    }
}

__global__ __launch_bounds__(256) void prep_kernel(
    const float* __restrict__ x, const float* __restrict__ Wq,
    const float* __restrict__ Wk, const float* __restrict__ Wv,
    const float* __restrict__ Wo)
{
    __shared__ float t[32][33];
    const int bx = blockIdx.x;
    if (bx < 4096) {
        const int n4 = MROWS * DM / 4;
        for (int i = bx * 256 + threadIdx.x; i < n4; i += 4096 * 256) {
            float4 v = ((const float4*)x)[i];
            __nv_bfloat16 h0, h1, h2, h3, l0, l1, l2, l3;
            split1(v.x, h0, l0); split1(v.y, h1, l1);
            split1(v.z, h2, l2); split1(v.w, h3, l3);
            uint2 H, L;
            H.x = pk2(h0, h1); H.y = pk2(h2, h3);
            L.x = pk2(l0, l1); L.y = pk2(l2, l3);
            ((uint2*)g_xhi)[i] = H;
            ((uint2*)g_xlo)[i] = L;
        }
    } else if (bx < 8192) {
        do_tsplit(Wq, g_wqhi, g_wqlo, DM, DM, bx - 4096, t);
    } else if (bx < 8448) {
        do_tsplit(Wk, g_wkhi, g_wklo, DM, DH, bx - 8192, t);
    } else if (bx < 8704) {
        do_tsplit(Wv, g_wvhi, g_wvlo, DM, DH, bx - 8448, t);
    } else {
        do_tsplit(Wo, g_wohi, g_wolo, DM, DM, bx - 8704, t);
    }
}

// ============================================================
// mma.sync bf16x3 GEMM. fused==1: QKV projection in one grid
// (bx<16 -> Q col tiles; bx==16 -> K; bx==17 -> V transposed-out).
// fused==0: O projection (fp32 out to Cext).
// ============================================================
#define STG 40960
#define OAH 0
#define OAL 10240
#define OBH 20480
#define OBL 30720

__global__ __launch_bounds__(256, 2) void tc_gemm(
    const float* __restrict__ b0, const float* __restrict__ b1,
    const float* __restrict__ b2, float* __restrict__ Cext,
    int asel, int fused)
{
    extern __shared__ char sm[];
    const uint32_t sbase = smem_u32(sm);
    const int tid = threadIdx.x;
    const int lane = tid & 31, warp = tid >> 5;
    const int wm = warp & 3, wn = warp >> 2;
    const int bx = blockIdx.x;
    const int rowBase = blockIdx.y * 128;

    const __nv_bfloat16* Ahi = asel ? g_chi : g_xhi;
    const __nv_bfloat16* Alo = asel ? g_clo : g_xlo;
    const __nv_bfloat16 *Bhi, *Blo;
    int wRow0;
    if (fused) {
        if (bx < 16)       { Bhi = g_wqhi; Blo = g_wqlo; wRow0 = bx * 128; }
        else if (bx == 16) { Bhi = g_wkhi; Blo = g_wklo; wRow0 = 0; }
        else               { Bhi = g_wvhi; Blo = g_wvlo; wRow0 = 0; }
    } else                 { Bhi = g_wohi; Blo = g_wolo; wRow0 = bx * 128; }

    float acc[2][8][4];
#pragma unroll
    for (int mt = 0; mt < 2; mt++)
#pragma unroll
        for (int nt = 0; nt < 8; nt++)
#pragma unroll
            for (int e = 0; e < 4; e++) acc[mt][nt][e] = 0.f;

    const int lr = tid >> 2, lc = tid & 3;
    const int a_r = lane & 15;
    const uint32_t a_kb = (lane & 16) ? 16 : 0;
    const int b_n = (lane & 7) + ((lane & 16) ? 8 : 0);
    const uint32_t b_kb = (lane & 8) ? 16 : 0;

#define LOAD_STAGE(buf, k0) do { \
    const uint32_t sb_ = sbase + (buf) * STG; \
    _Pragma("unroll") \
    for (int h_ = 0; h_ < 2; h_++) { \
        const int r_ = lr + h_ * 64; \
        const uint32_t so_ = r_ * 80 + lc * 16; \
        const size_t ga_ = (size_t)(rowBase + r_) * DM + (k0) + lc * 8; \
        const size_t gb_ = (size_t)(wRow0 + r_) * DM + (k0) + lc * 8; \
        CP16(sb_ + OAH + so_, Ahi + ga_); \
        CP16(sb_ + OAL + so_, Alo + ga_); \
        CP16(sb_ + OBH + so_, Bhi + gb_); \
        CP16(sb_ + OBL + so_, Blo + gb_); \
    } \
} while (0)

    LOAD_STAGE(0, 0);
    CP_COMMIT();

    const int ITERS = DM / 32;
    for (int s = 0; s < ITERS; s++) {
        if (s + 1 < ITERS) { LOAD_STAGE((s + 1) & 1, (s + 1) * 32); CP_COMMIT(); CP_WAIT1(); }
        else               { CP_WAIT0(); }
        __syncthreads();

        const uint32_t sb = sbase + (s & 1) * STG;
#pragma unroll
        for (int ks = 0; ks < 2; ks++) {
            const uint32_t kso = ks * 32;
            uint32_t ah[2][4], bb[8][2];
#pragma unroll
            for (int mt = 0; mt < 2; mt++) {
                const uint32_t addr = sb + OAH + (wm * 32 + mt * 16 + a_r) * 80 + kso + a_kb;
                ldsm_x4(ah[mt][0], ah[mt][1], ah[mt][2], ah[mt][3], addr);
            }
#pragma unroll
            for (int p = 0; p < 4; p++) {
                const uint32_t addr = sb + OBH + (wn * 64 + p * 16 + b_n) * 80 + kso + b_kb;
                ldsm_x4(bb[p * 2][0], bb[p * 2][1], bb[p * 2 + 1][0], bb[p * 2 + 1][1], addr);
            }
#pragma unroll
            for (int mt = 0; mt < 2; mt++)
#pragma unroll
                for (int nt = 0; nt < 8; nt++)
                    mma16816(acc[mt][nt], ah[mt], bb[nt]);
            {
                uint32_t al[2][4];
#pragma unroll
                for (int mt = 0; mt < 2; mt++) {
                    const uint32_t addr = sb + OAL + (wm * 32 + mt * 16 + a_r) * 80 + kso + a_kb;
                    ldsm_x4(al[mt][0], al[mt][1], al[mt][2], al[mt][3], addr);
                }
#pragma unroll
                for (int mt = 0; mt < 2; mt++)
#pragma unroll
                    for (int nt = 0; nt < 8; nt++)
                        mma16816(acc[mt][nt], al[mt], bb[nt]);
            }
#pragma unroll
            for (int p = 0; p < 4; p++) {
                const uint32_t addr = sb + OBL + (wn * 64 + p * 16 + b_n) * 80 + kso + b_kb;
                ldsm_x4(bb[p * 2][0], bb[p * 2][1], bb[p * 2 + 1][0], bb[p * 2 + 1][1], addr);
            }
#pragma unroll
            for (int mt = 0; mt < 2; mt++)
#pragma unroll
                for (int nt = 0; nt < 8; nt++)
                    mma16816(acc[mt][nt], ah[mt], bb[nt]);
        }
        __syncthreads();
    }

    const int g = lane >> 2, t2 = lane & 3;
    if (!fused) {
#pragma unroll
        for (int mt = 0; mt < 2; mt++) {
            const int r0 = rowBase + wm * 32 + mt * 16 + g;
#pragma unroll
            for (int nt = 0; nt < 8; nt++) {
                const int col = bx * 128 + wn * 64 + nt * 8 + t2 * 2;
                const float bxv = b0[col], byv = b0[col + 1];
                float2 o0, o1;
                o0.x = acc[mt][nt][0] + bxv; o0.y = acc[mt][nt][1] + byv;
                o1.x = acc[mt][nt][2] + bxv; o1.y = acc[mt][nt][3] + byv;
                *(float2*)(Cext + (size_t)r0 * DM + col) = o0;
                *(float2*)(Cext + (size_t)(r0 + 8) * DM + col) = o1;
            }
        }
    } else if (bx < 16) {
#pragma unroll
        for (int mt = 0; mt < 2; mt++) {
            const int r0 = rowBase + wm * 32 + mt * 16 + g;
#pragma unroll
            for (int nt = 0; nt < 8; nt++) {
                const int col = bx * 128 + wn * 64 + nt * 8 + t2 * 2;
                const float bxv = b0[col], byv = b0[col + 1];
                const float v0 = acc[mt][nt][0] + bxv, v1 = acc[mt][nt][1] + byv;
                const float v2 = acc[mt][nt][2] + bxv, v3 = acc[mt][nt][3] + byv;
                *(uint32_t*)&g_qhi[(size_t)r0 * DM + col] = splitpk_hi(v0, v1);
                *(uint32_t*)&g_qlo[(size_t)r0 * DM + col] = splitpk_lo(v0, v1);
                *(uint32_t*)&g_qhi[(size_t)(r0 + 8) * DM + col] = splitpk_hi(v2, v3);
                *(uint32_t*)&g_qlo[(size_t)(r0 + 8) * DM + col] = splitpk_lo(v2, v3);
            }
        }
    } else if (bx == 16) {
#pragma unroll
        for (int mt = 0; mt < 2; mt++) {
            const int r0 = rowBase + wm * 32 + mt * 16 + g;
#pragma unroll
            for (int nt = 0; nt < 8; nt++) {
                const int col = wn * 64 + nt * 8 + t2 * 2;
                const float bxv = b1[col], byv = b1[col + 1];
                const float v0 = acc[mt][nt][0] + bxv, v1 = acc[mt][nt][1] + byv;
                const float v2 = acc[mt][nt][2] + bxv, v3 = acc[mt][nt][3] + byv;
                *(uint32_t*)&g_khi[(size_t)r0 * DH + col] = splitpk_hi(v0, v1);
                *(uint32_t*)&g_klo[(size_t)r0 * DH + col] = splitpk_lo(v0, v1);
                *(uint32_t*)&g_khi[(size_t)(r0 + 8) * DH + col] = splitpk_hi(v2, v3);
                *(uint32_t*)&g_klo[(size_t)(r0 + 8) * DH + col] = splitpk_lo(v2, v3);
            }
        }
    } else {
        // V: write split values directly TRANSPOSED -> g_vthi/g_vtlo [b][d][t]
#pragma unroll
        for (int mt = 0; mt < 2; mt++) {
            const int r0 = rowBase + wm * 32 + mt * 16 + g;   // global token row
            const int bidx = r0 >> 11;                         // r0 / TT
            const int trow = r0 & (TT - 1);
#pragma unroll
            for (int nt = 0; nt < 8; nt++) {
                const int col = wn * 64 + nt * 8 + t2 * 2;
                const float bxv = b2[col], byv = b2[col + 1];
                const float v0 = acc[mt][nt][0] + bxv, v1 = acc[mt][nt][1] + byv;
                const float v2 = acc[mt][nt][2] + bxv, v3 = acc[mt][nt][3] + byv;
                const size_t base0 = ((size_t)bidx * DH + col) * TT + trow;
                __nv_bfloat16 h, l;
                split1(v0, h, l); g_vthi[base0] = h;          g_vtlo[base0] = l;
                split1(v1, h, l); g_vthi[base0 + TT] = h;     g_vtlo[base0 + TT] = l;
                split1(v2, h, l); g_vthi[base0 + 8] = h;      g_vtlo[base0 + 8] = l;
                split1(v3, h, l); g_vthi[base0 + TT + 8] = h; g_vtlo[base0 + TT + 8] = l;
            }
        }
    }
}

// ============================================================
// Flash attention: 128-thr CTAs, BN=32, 2 CTAs/SM; mma reordered
// for dependency distance 4 (RAW-chain test).
// ============================================================
#define AQS 272
#define AVS 80
#define QREG 34816
#define SKV 37888
#define ASMEM (QREG + 2 * SKV)   // 110592

__global__ __launch_bounds__(128, 2) void attn_mma()
{
    extern __shared__ char sm[];
    const uint32_t sb0 = smem_u32(sm);
    const int qt = gridDim.x - 1 - blockIdx.x;
    const int h = blockIdx.y, b = blockIdx.z;
    const int tid = threadIdx.x, lane = tid & 31, w = tid >> 5;
    const int g = lane >> 2, t2 = lane & 3;
    const int a_r = lane & 15;
    const uint32_t a_kb = (lane & 16) ? 16 : 0;
    const int b_n = (lane & 7) + ((lane & 16) ? 8 : 0);
    const uint32_t b_kb = (lane & 8) ? 16 : 0;

    {
        const size_t qbase = (size_t)(b * TT + qt * 64) * DM + h * DH;
#pragma unroll
        for (int j = 0; j < 8; j++) {
            const int n = tid + j * 128;
            const int row = n >> 4, ch = n & 15;
            const size_t gq = qbase + (size_t)row * DM + ch * 8;
            CP16(sb0 + row * AQS + ch * 16, g_qhi + gq);
            CP16(sb0 + 17408 + row * AQS + ch * 16, g_qlo + gq);
        }
    }
    CP_COMMIT();
    CP_WAIT0();
    __syncthreads();

    uint32_t aQh[8][4], aQl[8][4];
#pragma unroll
    for (int kt = 0; kt < 8; kt++) {
        const uint32_t qaddr = sb0 + (w * 16 + a_r) * AQS + kt * 32 + a_kb;
        ldsm_x4(aQh[kt][0], aQh[kt][1], aQh[kt][2], aQh[kt][3], qaddr);
        ldsm_x4(aQl[kt][0], aQl[kt][1], aQl[kt][2], aQl[kt][3], qaddr + 17408);
    }

#define LOADKV(buf, kb) do { \
    const uint32_t kvb_ = sb0 + QREG + (buf) * SKV; \
    const size_t kbase_ = (size_t)(b * TT + (kb) * 32) * DH; \
    const size_t vbase_ = (size_t)b * DH * TT + (size_t)(kb) * 32; \
    _Pragma("unroll") \
    for (int j_ = 0; j_ < 4; j_++) { \
        const int n_ = tid + j_ * 128; \
        const int kr_ = n_ >> 4, kc_ = n_ & 15; \
        const size_t gk_ = kbase_ + (size_t)kr_ * DH + kc_ * 8; \
        CP16(kvb_ + kr_ * AQS + kc_ * 16, g_khi + gk_); \
        CP16(kvb_ + 8704 + kr_ * AQS + kc_ * 16, g_klo + gk_); \
        const int vr_ = n_ >> 2, vc_ = n_ & 3; \
        const size_t gv_ = vbase_ + (size_t)vr_ * TT + vc_ * 8; \
        CP16(kvb_ + 17408 + vr_ * AVS + vc_ * 16, g_vthi + gv_); \
        CP16(kvb_ + 27648 + vr_ * AVS + vc_ * 16, g_vtlo + gv_); \
    } \
} while (0)

    const int ntiles = 2 * qt + 2;
    LOADKV(0, 0);
    CP_COMMIT();

    float O[16][4];
#pragma unroll
    for (int i = 0; i < 16; i++)
#pragma unroll
        for (int e = 0; e < 4; e++) O[i][e] = 0.f;
    float m0 = -1e30f, m1 = -1e30f, l0 = 0.f, l1 = 0.f;
    const float sc2 = 0.08838834764831845f * 1.4426950408889634f;
    const int qrow0 = qt * 64 + w * 16 + g;
    const int wrow_max = qt * 64 + w * 16 + 15;

    for (int it = 0; it < ntiles; it++) {
        if (it + 1 < ntiles) { LOADKV((it + 1) & 1, it + 1); CP_COMMIT(); CP_WAIT1(); }
        else                 { CP_WAIT0(); }
        __syncthreads();
        const uint32_t kvb = sb0 + QREG + (it & 1) * SKV;

        if (it * 32 <= wrow_max) {
            // ---- S = Q K^T (x3), distance-4 accumulation ----
            float sS[4][4];
#pragma unroll
            for (int i = 0; i < 4; i++)
#pragma unroll
                for (int e = 0; e < 4; e++) sS[i][e] = 0.f;
#pragma unroll
            for (int kt = 0; kt < 8; kt++) {
                uint32_t kbh[4][2], kbl[4][2];
#pragma unroll
                for (int p = 0; p < 2; p++) {
                    const uint32_t kaddr = kvb + (p * 16 + b_n) * AQS + kt * 32 + b_kb;
                    ldsm_x4(kbh[2 * p][0], kbh[2 * p][1],
                            kbh[2 * p + 1][0], kbh[2 * p + 1][1], kaddr);
                    ldsm_x4(kbl[2 * p][0], kbl[2 * p][1],
                            kbl[2 * p + 1][0], kbl[2 * p + 1][1], kaddr + 8704);
                }
#pragma unroll
                for (int nt = 0; nt < 4; nt++) mma16816(sS[nt], aQh[kt], kbh[nt]);
#pragma unroll
                for (int nt = 0; nt < 4; nt++) mma16816(sS[nt], aQl[kt], kbh[nt]);
#pragma unroll
                for (int nt = 0; nt < 4; nt++) mma16816(sS[nt], aQh[kt], kbl[nt]);
            }

            // ---- online softmax (log2 domain) ----
            const int kcol0 = it * 32 + 2 * t2;
            float ml0 = -1e30f, ml1 = -1e30f;
#pragma unroll
            for (int nt = 0; nt < 4; nt++) {
                const int c = kcol0 + nt * 8;
                float s0 = sS[nt][0] * sc2, s1 = sS[nt][1] * sc2;
                float s2 = sS[nt][2] * sc2, s3 = sS[nt][3] * sc2;
                if (c > qrow0)         s0 = -1e30f;
                if (c + 1 > qrow0)     s1 = -1e30f;
                if (c > qrow0 + 8)     s2 = -1e30f;
                if (c + 1 > qrow0 + 8) s3 = -1e30f;
                sS[nt][0] = s0; sS[nt][1] = s1; sS[nt][2] = s2; sS[nt][3] = s3;
                ml0 = fmaxf(ml0, fmaxf(s0, s1));
                ml1 = fmaxf(ml1, fmaxf(s2, s3));
            }
            ml0 = fmaxf(ml0, __shfl_xor_sync(0xffffffffu, ml0, 1));
            ml0 = fmaxf(ml0, __shfl_xor_sync(0xffffffffu, ml0, 2));
            ml1 = fmaxf(ml1, __shfl_xor_sync(0xffffffffu, ml1, 1));
            ml1 = fmaxf(ml1, __shfl_xor_sync(0xffffffffu, ml1, 2));
            const float mn0 = fmaxf(m0, ml0), mn1 = fmaxf(m1, ml1);
            const float al0 = ex2f(m0 - mn0), al1 = ex2f(m1 - mn1);

            float ps0 = 0.f, ps1 = 0.f;
            uint32_t aPh[2][4], aPl[2][4];
#pragma unroll
            for (int u = 0; u < 2; u++) {
                const float p00 = ex2f(sS[2 * u][0] - mn0);
                const float p01 = ex2f(sS[2 * u][1] - mn0);
                const float p02 = ex2f(sS[2 * u][2] - mn1);
                const float p03 = ex2f(sS[2 * u][3] - mn1);
                const float p10 = ex2f(sS[2 * u + 1][0] - mn0);
                const float p11 = ex2f(sS[2 * u + 1][1] - mn0);
                const float p12 = ex2f(sS[2 * u + 1][2] - mn1);
                const float p13 = ex2f(sS[2 * u + 1][3] - mn1);
                ps0 += p00 + p01 + p10 + p11;
                ps1 += p02 + p03 + p12 + p13;
                aPh[u][0] = splitpk_hi(p00, p01); aPl[u][0] = splitpk_lo(p00, p01);
                aPh[u][1] = splitpk_hi(p02, p03); aPl[u][1] = splitpk_lo(p02, p03);
                aPh[u][2] = splitpk_hi(p10, p11); aPl[u][2] = splitpk_lo(p10, p11);
                aPh[u][3] = splitpk_hi(p12, p13); aPl[u][3] = splitpk_lo(p12, p13);
            }
            ps0 += __shfl_xor_sync(0xffffffffu, ps0, 1);
            ps0 += __shfl_xor_sync(0xffffffffu, ps0, 2);
            ps1 += __shfl_xor_sync(0xffffffffu, ps1, 1);
            ps1 += __shfl_xor_sync(0xffffffffu, ps1, 2);
            l0 = l0 * al0 + ps0;
            l1 = l1 * al1 + ps1;
            m0 = mn0; m1 = mn1;
#pragma unroll
            for (int i = 0; i < 16; i++) {
                O[i][0] *= al0; O[i][1] *= al0;
                O[i][2] *= al1; O[i][3] *= al1;
            }

            // ---- O += P V (x3), distance-4 accumulation ----
#pragma unroll
            for (int u = 0; u < 2; u++) {
#pragma unroll
                for (int pp = 0; pp < 4; pp++) {
                    uint32_t vbh[4][2], vbl[4][2];
#pragma unroll
                    for (int pi = 0; pi < 2; pi++) {
                        const int p = 2 * pp + pi;
                        const uint32_t vaddr =
                            kvb + 17408 + (p * 16 + b_n) * AVS + u * 32 + b_kb;
                        ldsm_x4(vbh[2 * pi][0], vbh[2 * pi][1],
                                vbh[2 * pi + 1][0], vbh[2 * pi + 1][1], vaddr);
                        ldsm_x4(vbl[2 * pi][0], vbl[2 * pi][1],
                                vbl[2 * pi + 1][0], vbl[2 * pi + 1][1], vaddr + 10240);
                    }
#pragma unroll
                    for (int q = 0; q < 4; q++) mma16816(O[4 * pp + q], aPh[u], vbh[q]);
#pragma unroll
                    for (int q = 0; q < 4; q++) mma16816(O[4 * pp + q], aPl[u], vbh[q]);
#pragma unroll
                    for (int q = 0; q < 4; q++) mma16816(O[4 * pp + q], aPh[u], vbl[q]);
                }
            }
        }
        __syncthreads();
    }

    const float inv0 = 1.0f / l0, inv1 = 1.0f / l1;
    const size_t obase = (size_t)(b * TT + qrow0) * DM + h * DH;
#pragma unroll
    for (int ntd = 0; ntd < 16; ntd++) {
        const int d = ntd * 8 + 2 * t2;
        const float v0 = O[ntd][0] * inv0, v1 = O[ntd][1] * inv0;
        const float v2 = O[ntd][2] * inv1, v3 = O[ntd][3] * inv1;
        *(uint32_t*)&g_chi[obase + d] = splitpk_hi(v0, v1);
        *(uint32_t*)&g_clo[obase + d] = splitpk_lo(v0, v1);
        *(uint32_t*)&g_chi[obase + 8 * DM + d] = splitpk_hi(v2, v3);
        *(uint32_t*)&g_clo[obase + 8 * DM + d] = splitpk_lo(v2, v3);
    }
}

// ============================================================
extern "C" void kernel_launch(void* const* d_in, const int* in_sizes, int n_in,
                              void* d_out, int out_size)
{
    const float* x  = (const float*)d_in[0];
    const float* Wq = (const float*)d_in[2];
    const float* bq = (const float*)d_in[3];
    const float* Wk = (const float*)d_in[4];
    const float* bk = (const float*)d_in[5];
    const float* Wv = (const float*)d_in[6];
    const float* bv = (const float*)d_in[7];
    const float* Wo = (const float*)d_in[8];
    const float* bo = (const float*)d_in[9];
    float* out = (float*)d_out;

    const int gsmem = 2 * STG;
    cudaFuncSetAttribute(tc_gemm, cudaFuncAttributeMaxDynamicSharedMemorySize, gsmem);
    cudaFuncSetAttribute(attn_mma, cudaFuncAttributeMaxDynamicSharedMemorySize, ASMEM);

    prep_kernel<<<12800, 256>>>(x, Wq, Wk, Wv, Wo);

    // fused Q|K|V projection (V emits transposed split directly)
    tc_gemm<<<dim3(18, MROWS / 128), 256, gsmem>>>(bq, bk, bv, nullptr, 0, 1);

    attn_mma<<<dim3(TT / 64, NH, BBAT), 128, ASMEM>>>();

    tc_gemm<<<dim3(16, MROWS / 128), 256, gsmem>>>(bo, nullptr, nullptr, out, 1, 0);
}

// round 12
// speedup vs baseline: 1.1883x; 1.1883x over previous
#include <cuda_runtime.h>
#include <cuda_bf16.h>
#include <cuda_fp16.h>
#include <cstdint>

#define BBAT 4
#define TT 2048
#define DM 2048
#define NH 16
#define DH 128
#define MROWS (BBAT * TT)

// ---- scratch ----
__device__ __nv_bfloat16 g_xhi[(size_t)MROWS * DM], g_xlo[(size_t)MROWS * DM];  // bf16 x (K/V path)
__device__ __half        g_xfh[(size_t)MROWS * DM], g_xfl[(size_t)MROWS * DM];  // fp16 x (Q path)
__device__ __nv_bfloat16 g_chi[(size_t)MROWS * DM], g_clo[(size_t)MROWS * DM];  // ctx bf16 split
__device__ __half        g_qfh[(size_t)MROWS * DM], g_qfl[(size_t)MROWS * DM];  // Q fp16 split
__device__ __half        g_k[(size_t)MROWS * DH];                               // K single fp16
__device__ __half        g_vt[(size_t)DH * MROWS];                              // V single fp16, [b][d][t]
__device__ __half        g_wq[(size_t)DM * DM];                                 // Wq single fp16 [N][K]
__device__ __nv_bfloat16 g_wkhi[(size_t)DH * DM], g_wklo[(size_t)DH * DM];
__device__ __nv_bfloat16 g_wvhi[(size_t)DH * DM], g_wvlo[(size_t)DH * DM];
__device__ __nv_bfloat16 g_wohi[(size_t)DM * DM], g_wolo[(size_t)DM * DM];

// ---- PTX helpers ----
__device__ __forceinline__ uint32_t smem_u32(const void* p) {
    uint32_t a;
    asm("{ .reg .u64 t; cvta.to.shared.u64 t, %1; cvt.u32.u64 %0, t; }" : "=r"(a) : "l"(p));
    return a;
}
#define CP16(s, g) \
    asm volatile("cp.async.cg.shared.global [%0], [%1], 16;" :: "r"(s), "l"(g))
#define CP_COMMIT() asm volatile("cp.async.commit_group;" ::: "memory")
#define CP_WAIT1() asm volatile("cp.async.wait_group 1;" ::: "memory")
#define CP_WAIT0() asm volatile("cp.async.wait_group 0;" ::: "memory")

__device__ __forceinline__ void ldsm_x4(uint32_t& r0, uint32_t& r1, uint32_t& r2,
                                        uint32_t& r3, uint32_t addr) {
    asm volatile("ldmatrix.sync.aligned.m8n8.x4.shared.b16 {%0,%1,%2,%3}, [%4];"
                 : "=r"(r0), "=r"(r1), "=r"(r2), "=r"(r3) : "r"(addr));
}
__device__ __forceinline__ void mma_bf(float* c, const uint32_t* a, const uint32_t* b) {
    asm volatile("mma.sync.aligned.m16n8k16.row.col.f32.bf16.bf16.f32 "
                 "{%0,%1,%2,%3}, {%4,%5,%6,%7}, {%8,%9}, {%0,%1,%2,%3};"
                 : "+f"(c[0]), "+f"(c[1]), "+f"(c[2]), "+f"(c[3])
                 : "r"(a[0]), "r"(a[1]), "r"(a[2]), "r"(a[3]), "r"(b[0]), "r"(b[1]));
}
__device__ __forceinline__ void mma_f16(float* c, const uint32_t* a, const uint32_t* b) {
    asm volatile("mma.sync.aligned.m16n8k16.row.col.f32.f16.f16.f32 "
                 "{%0,%1,%2,%3}, {%4,%5,%6,%7}, {%8,%9}, {%0,%1,%2,%3};"
                 : "+f"(c[0]), "+f"(c[1]), "+f"(c[2]), "+f"(c[3])
                 : "r"(a[0]), "r"(a[1]), "r"(a[2]), "r"(a[3]), "r"(b[0]), "r"(b[1]));
}
__device__ __forceinline__ float ex2f(float x) {
    float y;
    asm("ex2.approx.f32 %0, %1;" : "=f"(y) : "f"(x));
    return y;
}

// ---- splits ----
__device__ __forceinline__ void split1(float v, __nv_bfloat16& h, __nv_bfloat16& l) {
    h = __float2bfloat16(v);
    l = __float2bfloat16(v - __bfloat162float(h));
}
__device__ __forceinline__ uint32_t pk2(__nv_bfloat16 a, __nv_bfloat16 b) {
    return (uint32_t)__bfloat16_as_ushort(a) | ((uint32_t)__bfloat16_as_ushort(b) << 16);
}
__device__ __forceinline__ uint32_t splitpk_hi(float a, float b) {
    return pk2(__float2bfloat16(a), __float2bfloat16(b));
}
__device__ __forceinline__ uint32_t splitpk_lo(float a, float b) {
    __nv_bfloat16 ha = __float2bfloat16(a), hb = __float2bfloat16(b);
    return pk2(__float2bfloat16(a - __bfloat162float(ha)),
               __float2bfloat16(b - __bfloat162float(hb)));
}
__device__ __forceinline__ uint32_t pk2h(__half a, __half b) {
    return (uint32_t)__half_as_ushort(a) | ((uint32_t)__half_as_ushort(b) << 16);
}
__device__ __forceinline__ uint32_t spkh_hi(float a, float b) {
    return pk2h(__float2half_rn(a), __float2half_rn(b));
}
__device__ __forceinline__ uint32_t spkh_lo(float a, float b) {
    __half ha = __float2half_rn(a), hb = __float2half_rn(b);
    return pk2h(__float2half_rn(a - __half2float(ha)),
                __float2half_rn(b - __half2float(hb)));
}

// ============================================================
// Fused prep:
//  [0,4096)      x -> bf16 hi/lo + fp16 hi/lo
//  [4096,8192)   Wq -> single fp16 transposed
//  [8192,8448)   Wk -> bf16 hi/lo transposed
//  [8448,8704)   Wv -> bf16 hi/lo transposed
//  [8704,12800)  Wo -> bf16 hi/lo transposed
// ============================================================
__device__ __forceinline__ void do_tsplit(const float* __restrict__ W,
                                          __nv_bfloat16* hi, __nv_bfloat16* lo,
                                          int Kd, int Nd, int bx2, float (*t)[33]) {
    const int xw = Nd / 32;
    const int nb = (bx2 % xw) * 32, kb = (bx2 / xw) * 32;
    const int tx = threadIdx.x & 31, ty = threadIdx.x >> 5;
#pragma unroll
    for (int i = 0; i < 4; i++)
        t[ty + 8 * i][tx] = W[(size_t)(kb + ty + 8 * i) * Nd + nb + tx];
    __syncthreads();
#pragma unroll
    for (int i = 0; i < 4; i++) {
        const int nrow = ty + 8 * i;
        __nv_bfloat16 h, l;
        split1(t[tx][nrow], h, l);
        const size_t o = (size_t)(nb + nrow) * Kd + kb + tx;
        hi[o] = h; lo[o] = l;
    }
}
__device__ __forceinline__ void do_tsingle_h(const float* __restrict__ W,
                                             __half* dst, int Kd, int Nd, int bx2,
                                             float (*t)[33]) {
    const int xw = Nd / 32;
    const int nb = (bx2 % xw) * 32, kb = (bx2 / xw) * 32;
    const int tx = threadIdx.x & 31, ty = threadIdx.x >> 5;
#pragma unroll
    for (int i = 0; i < 4; i++)
        t[ty + 8 * i][tx] = W[(size_t)(kb + ty + 8 * i) * Nd + nb + tx];
    __syncthreads();
#pragma unroll
    for (int i = 0; i < 4; i++) {
        const int nrow = ty + 8 * i;
        dst[(size_t)(nb + nrow) * Kd + kb + tx] = __float2half_rn(t[tx][nrow]);
    }
}

__global__ __launch_bounds__(256) void prep_kernel(
    const float* __restrict__ x, const float* __restrict__ Wq,
    const float* __restrict__ Wk, const float* __restrict__ Wv,
    const float* __restrict__ Wo)
{
    __shared__ float t[32][33];
    const int bx = blockIdx.x;
    if (bx < 4096) {
        const int n4 = MROWS * DM / 4;
        for (int i = bx * 256 + threadIdx.x; i < n4; i += 4096 * 256) {
            float4 v = ((const float4*)x)[i];
            __nv_bfloat16 h0, h1, h2, h3, l0, l1, l2, l3;
            split1(v.x, h0, l0); split1(v.y, h1, l1);
            split1(v.z, h2, l2); split1(v.w, h3, l3);
            uint2 H, L;
            H.x = pk2(h0, h1); H.y = pk2(h2, h3);
            L.x = pk2(l0, l1); L.y = pk2(l2, l3);
            ((uint2*)g_xhi)[i] = H;
            ((uint2*)g_xlo)[i] = L;
            uint2 FH, FL;
            FH.x = spkh_hi(v.x, v.y); FH.y = spkh_hi(v.z, v.w);
            __half hx = __float2half_rn(v.x), hy = __float2half_rn(v.y);
            __half hz = __float2half_rn(v.z), hw = __float2half_rn(v.w);
            FL.x = pk2h(__float2half_rn(v.x - __half2float(hx)),
                        __float2half_rn(v.y - __half2float(hy)));
            FL.y = pk2h(__float2half_rn(v.z - __half2float(hz)),
                        __float2half_rn(v.w - __half2float(hw)));
            ((uint2*)g_xfh)[i] = FH;
            ((uint2*)g_xfl)[i] = FL;
        }
    } else if (bx < 8192) {
        do_tsingle_h(Wq, g_wq, DM, DM, bx - 4096, t);
    } else if (bx < 8448) {
        do_tsplit(Wk, g_wkhi, g_wklo, DM, DH, bx - 8192, t);
    } else if (bx < 8704) {
        do_tsplit(Wv, g_wvhi, g_wvlo, DM, DH, bx - 8448, t);
    } else {
        do_tsplit(Wo, g_wohi, g_wolo, DM, DM, bx - 8704, t);
    }
}

// ============================================================
// QKV projection: bx<16 -> Q (fp16 2-pass); bx==16 -> K (bf16x3);
// bx==17 -> V (bf16x3, transposed fp16 out).
// ============================================================
#define STG 40960

__global__ __launch_bounds__(256, 2) void tc_gemm_qkv(
    const float* __restrict__ bq, const float* __restrict__ bk,
    const float* __restrict__ bv)
{
    extern __shared__ char sm[];
    const uint32_t sbase = smem_u32(sm);
    const int tid = threadIdx.x;
    const int lane = tid & 31, warp = tid >> 5;
    const int wm = warp & 3, wn = warp >> 2;
    const int bx = blockIdx.x;
    const int rowBase = blockIdx.y * 128;

    const int lr = tid >> 2, lc = tid & 3;
    const int a_r = lane & 15;
    const uint32_t a_kb = (lane & 16) ? 16 : 0;
    const int b_n = (lane & 7) + ((lane & 16) ? 8 : 0);
    const uint32_t b_kb = (lane & 8) ? 16 : 0;
    const int g = lane >> 2, t2 = lane & 3;
    const int ITERS = DM / 32;

    float acc[2][8][4];
#pragma unroll
    for (int mt = 0; mt < 2; mt++)
#pragma unroll
        for (int nt = 0; nt < 8; nt++)
#pragma unroll
            for (int e = 0; e < 4; e++) acc[mt][nt][e] = 0.f;

    if (bx < 16) {
        // ---------- Q: fp16 2-pass ----------
        const int wRow0 = bx * 128;
#define LOADQ(buf, k0) do { \
    const uint32_t sb_ = sbase + (buf) * STG; \
    _Pragma("unroll") \
    for (int h_ = 0; h_ < 2; h_++) { \
        const int r_ = lr + h_ * 64; \
        const uint32_t so_ = r_ * 80 + lc * 16; \
        const size_t ga_ = (size_t)(rowBase + r_) * DM + (k0) + lc * 8; \
        const size_t gb_ = (size_t)(wRow0 + r_) * DM + (k0) + lc * 8; \
        CP16(sb_ + so_, g_xfh + ga_); \
        CP16(sb_ + 10240 + so_, g_xfl + ga_); \
        CP16(sb_ + 20480 + so_, g_wq + gb_); \
    } \
} while (0)
        LOADQ(0, 0);
        CP_COMMIT();
        for (int s = 0; s < ITERS; s++) {
            if (s + 1 < ITERS) { LOADQ((s + 1) & 1, (s + 1) * 32); CP_COMMIT(); CP_WAIT1(); }
            else               { CP_WAIT0(); }
            __syncthreads();
            const uint32_t sb = sbase + (s & 1) * STG;
#pragma unroll
            for (int ks = 0; ks < 2; ks++) {
                const uint32_t kso = ks * 32;
                uint32_t ah[2][4], al[2][4], bb[8][2];
#pragma unroll
                for (int mt = 0; mt < 2; mt++) {
                    const uint32_t addr = sb + (wm * 32 + mt * 16 + a_r) * 80 + kso + a_kb;
                    ldsm_x4(ah[mt][0], ah[mt][1], ah[mt][2], ah[mt][3], addr);
                    ldsm_x4(al[mt][0], al[mt][1], al[mt][2], al[mt][3], addr + 10240);
                }
#pragma unroll
                for (int p = 0; p < 4; p++) {
                    const uint32_t addr =
                        sb + 20480 + (wn * 64 + p * 16 + b_n) * 80 + kso + b_kb;
                    ldsm_x4(bb[p * 2][0], bb[p * 2][1],
                            bb[p * 2 + 1][0], bb[p * 2 + 1][1], addr);
                }
#pragma unroll
                for (int mt = 0; mt < 2; mt++)
#pragma unroll
                    for (int nt = 0; nt < 8; nt++)
                        mma_f16(acc[mt][nt], ah[mt], bb[nt]);
#pragma unroll
                for (int mt = 0; mt < 2; mt++)
#pragma unroll
                    for (int nt = 0; nt < 8; nt++)
                        mma_f16(acc[mt][nt], al[mt], bb[nt]);
            }
            __syncthreads();
        }
        // epilogue: Q fp16 split
#pragma unroll
        for (int mt = 0; mt < 2; mt++) {
            const int r0 = rowBase + wm * 32 + mt * 16 + g;
#pragma unroll
            for (int nt = 0; nt < 8; nt++) {
                const int col = bx * 128 + wn * 64 + nt * 8 + t2 * 2;
                const float bxv = bq[col], byv = bq[col + 1];
                const float v0 = acc[mt][nt][0] + bxv, v1 = acc[mt][nt][1] + byv;
                const float v2 = acc[mt][nt][2] + bxv, v3 = acc[mt][nt][3] + byv;
                *(uint32_t*)&g_qfh[(size_t)r0 * DM + col] = spkh_hi(v0, v1);
                *(uint32_t*)&g_qfl[(size_t)r0 * DM + col] = spkh_lo(v0, v1);
                *(uint32_t*)&g_qfh[(size_t)(r0 + 8) * DM + col] = spkh_hi(v2, v3);
                *(uint32_t*)&g_qfl[(size_t)(r0 + 8) * DM + col] = spkh_lo(v2, v3);
            }
        }
    } else {
        // ---------- K/V: bf16 x3 ----------
        const __nv_bfloat16* Bhi = (bx == 16) ? g_wkhi : g_wvhi;
        const __nv_bfloat16* Blo = (bx == 16) ? g_wklo : g_wvlo;
#define LOADKVW(buf, k0) do { \
    const uint32_t sb_ = sbase + (buf) * STG; \
    _Pragma("unroll") \
    for (int h_ = 0; h_ < 2; h_++) { \
        const int r_ = lr + h_ * 64; \
        const uint32_t so_ = r_ * 80 + lc * 16; \
        const size_t ga_ = (size_t)(rowBase + r_) * DM + (k0) + lc * 8; \
        const size_t gb_ = (size_t)r_ * DM + (k0) + lc * 8; \
        CP16(sb_ + so_, g_xhi + ga_); \
        CP16(sb_ + 10240 + so_, g_xlo + ga_); \
        CP16(sb_ + 20480 + so_, Bhi + gb_); \
        CP16(sb_ + 30720 + so_, Blo + gb_); \
    } \
} while (0)
        LOADKVW(0, 0);
        CP_COMMIT();
        for (int s = 0; s < ITERS; s++) {
            if (s + 1 < ITERS) { LOADKVW((s + 1) & 1, (s + 1) * 32); CP_COMMIT(); CP_WAIT1(); }
            else               { CP_WAIT0(); }
            __syncthreads();
            const uint32_t sb = sbase + (s & 1) * STG;
#pragma unroll
            for (int ks = 0; ks < 2; ks++) {
                const uint32_t kso = ks * 32;
                uint32_t ah[2][4], bb[8][2];
#pragma unroll
                for (int mt = 0; mt < 2; mt++) {
                    const uint32_t addr = sb + (wm * 32 + mt * 16 + a_r) * 80 + kso + a_kb;
                    ldsm_x4(ah[mt][0], ah[mt][1], ah[mt][2], ah[mt][3], addr);
                }
#pragma unroll
                for (int p = 0; p < 4; p++) {
                    const uint32_t addr =
                        sb + 20480 + (wn * 64 + p * 16 + b_n) * 80 + kso + b_kb;
                    ldsm_x4(bb[p * 2][0], bb[p * 2][1],
                            bb[p * 2 + 1][0], bb[p * 2 + 1][1], addr);
                }
#pragma unroll
                for (int mt = 0; mt < 2; mt++)
#pragma unroll
                    for (int nt = 0; nt < 8; nt++)
                        mma_bf(acc[mt][nt], ah[mt], bb[nt]);
                {
                    uint32_t al[2][4];
#pragma unroll
                    for (int mt = 0; mt < 2; mt++) {
                        const uint32_t addr =
                            sb + 10240 + (wm * 32 + mt * 16 + a_r) * 80 + kso + a_kb;
                        ldsm_x4(al[mt][0], al[mt][1], al[mt][2], al[mt][3], addr);
                    }
#pragma unroll
                    for (int mt = 0; mt < 2; mt++)
#pragma unroll
                        for (int nt = 0; nt < 8; nt++)
                            mma_bf(acc[mt][nt], al[mt], bb[nt]);
                }
#pragma unroll
                for (int p = 0; p < 4; p++) {
                    const uint32_t addr =
                        sb + 30720 + (wn * 64 + p * 16 + b_n) * 80 + kso + b_kb;
                    ldsm_x4(bb[p * 2][0], bb[p * 2][1],
                            bb[p * 2 + 1][0], bb[p * 2 + 1][1], addr);
                }
#pragma unroll
                for (int mt = 0; mt < 2; mt++)
#pragma unroll
                    for (int nt = 0; nt < 8; nt++)
                        mma_bf(acc[mt][nt], ah[mt], bb[nt]);
            }
            __syncthreads();
        }
        if (bx == 16) {
            // K: single fp16, stride DH
#pragma unroll
            for (int mt = 0; mt < 2; mt++) {
                const int r0 = rowBase + wm * 32 + mt * 16 + g;
#pragma unroll
                for (int nt = 0; nt < 8; nt++) {
                    const int col = wn * 64 + nt * 8 + t2 * 2;
                    const float bxv = bk[col], byv = bk[col + 1];
                    const float v0 = acc[mt][nt][0] + bxv, v1 = acc[mt][nt][1] + byv;
                    const float v2 = acc[mt][nt][2] + bxv, v3 = acc[mt][nt][3] + byv;
                    *(uint32_t*)&g_k[(size_t)r0 * DH + col] = spkh_hi(v0, v1);
                    *(uint32_t*)&g_k[(size_t)(r0 + 8) * DH + col] = spkh_hi(v2, v3);
                }
            }
        } else {
            // V: single fp16, transposed [b][d][t]
#pragma unroll
            for (int mt = 0; mt < 2; mt++) {
                const int r0 = rowBase + wm * 32 + mt * 16 + g;
                const int bidx = r0 >> 11;
                const int trow = r0 & (TT - 1);
#pragma unroll
                for (int nt = 0; nt < 8; nt++) {
                    const int col = wn * 64 + nt * 8 + t2 * 2;
                    const float bxv = bv[col], byv = bv[col + 1];
                    const float v0 = acc[mt][nt][0] + bxv, v1 = acc[mt][nt][1] + byv;
                    const float v2 = acc[mt][nt][2] + bxv, v3 = acc[mt][nt][3] + byv;
                    const size_t base0 = ((size_t)bidx * DH + col) * TT + trow;
                    g_vt[base0]          = __float2half_rn(v0);
                    g_vt[base0 + TT]     = __float2half_rn(v1);
                    g_vt[base0 + 8]      = __float2half_rn(v2);
                    g_vt[base0 + TT + 8] = __float2half_rn(v3);
                }
            }
        }
    }
}

// ============================================================
// O projection: bf16 x3 (unchanged machinery), fp32 out.
// ============================================================
__global__ __launch_bounds__(256, 2) void tc_gemm_o(
    const float* __restrict__ bo, float* __restrict__ Cext)
{
    extern __shared__ char sm[];
    const uint32_t sbase = smem_u32(sm);
    const int tid = threadIdx.x;
    const int lane = tid & 31, warp = tid >> 5;
    const int wm = warp & 3, wn = warp >> 2;
    const int bx = blockIdx.x;
    const int rowBase = blockIdx.y * 128;
    const int wRow0 = bx * 128;

    float acc[2][8][4];
#pragma unroll
    for (int mt = 0; mt < 2; mt++)
#pragma unroll
        for (int nt = 0; nt < 8; nt++)
#pragma unroll
            for (int e = 0; e < 4; e++) acc[mt][nt][e] = 0.f;

    const int lr = tid >> 2, lc = tid & 3;
    const int a_r = lane & 15;
    const uint32_t a_kb = (lane & 16) ? 16 : 0;
    const int b_n = (lane & 7) + ((lane & 16) ? 8 : 0);
    const uint32_t b_kb = (lane & 8) ? 16 : 0;

#define LOADO(buf, k0) do { \
    const uint32_t sb_ = sbase + (buf) * STG; \
    _Pragma("unroll") \
    for (int h_ = 0; h_ < 2; h_++) { \
        const int r_ = lr + h_ * 64; \
        const uint32_t so_ = r_ * 80 + lc * 16; \
        const size_t ga_ = (size_t)(rowBase + r_) * DM + (k0) + lc * 8; \
        const size_t gb_ = (size_t)(wRow0 + r_) * DM + (k0) + lc * 8; \
        CP16(sb_ + so_, g_chi + ga_); \
        CP16(sb_ + 10240 + so_, g_clo + ga_); \
        CP16(sb_ + 20480 + so_, g_wohi + gb_); \
        CP16(sb_ + 30720 + so_, g_wolo + gb_); \
    } \
} while (0)

    LOADO(0, 0);
    CP_COMMIT();
    const int ITERS = DM / 32;
    for (int s = 0; s < ITERS; s++) {
        if (s + 1 < ITERS) { LOADO((s + 1) & 1, (s + 1) * 32); CP_COMMIT(); CP_WAIT1(); }
        else               { CP_WAIT0(); }
        __syncthreads();
        const uint32_t sb = sbase + (s & 1) * STG;
#pragma unroll
        for (int ks = 0; ks < 2; ks++) {
            const uint32_t kso = ks * 32;
            uint32_t ah[2][4], bb[8][2];
#pragma unroll
            for (int mt = 0; mt < 2; mt++) {
                const uint32_t addr = sb + (wm * 32 + mt * 16 + a_r) * 80 + kso + a_kb;
                ldsm_x4(ah[mt][0], ah[mt][1], ah[mt][2], ah[mt][3], addr);
            }
#pragma unroll
            for (int p = 0; p < 4; p++) {
                const uint32_t addr = sb + 20480 + (wn * 64 + p * 16 + b_n) * 80 + kso + b_kb;
                ldsm_x4(bb[p * 2][0], bb[p * 2][1], bb[p * 2 + 1][0], bb[p * 2 + 1][1], addr);
            }
#pragma unroll
            for (int mt = 0; mt < 2; mt++)
#pragma unroll
                for (int nt = 0; nt < 8; nt++)
                    mma_bf(acc[mt][nt], ah[mt], bb[nt]);
            {
                uint32_t al[2][4];
#pragma unroll
                for (int mt = 0; mt < 2; mt++) {
                    const uint32_t addr =
                        sb + 10240 + (wm * 32 + mt * 16 + a_r) * 80 + kso + a_kb;
                    ldsm_x4(al[mt][0], al[mt][1], al[mt][2], al[mt][3], addr);
                }
#pragma unroll
                for (int mt = 0; mt < 2; mt++)
#pragma unroll
                    for (int nt = 0; nt < 8; nt++)
                        mma_bf(acc[mt][nt], al[mt], bb[nt]);
            }
#pragma unroll
            for (int p = 0; p < 4; p++) {
                const uint32_t addr = sb + 30720 + (wn * 64 + p * 16 + b_n) * 80 + kso + b_kb;
                ldsm_x4(bb[p * 2][0], bb[p * 2][1], bb[p * 2 + 1][0], bb[p * 2 + 1][1], addr);
            }
#pragma unroll
            for (int mt = 0; mt < 2; mt++)
#pragma unroll
                for (int nt = 0; nt < 8; nt++)
                    mma_bf(acc[mt][nt], ah[mt], bb[nt]);
        }
        __syncthreads();
    }

    const int g = lane >> 2, t2 = lane & 3;
#pragma unroll
    for (int mt = 0; mt < 2; mt++) {
        const int r0 = rowBase + wm * 32 + mt * 16 + g;
#pragma unroll
        for (int nt = 0; nt < 8; nt++) {
            const int col = bx * 128 + wn * 64 + nt * 8 + t2 * 2;
            const float bxv = bo[col], byv = bo[col + 1];
            float2 o0, o1;
            o0.x = acc[mt][nt][0] + bxv; o0.y = acc[mt][nt][1] + byv;
            o1.x = acc[mt][nt][2] + bxv; o1.y = acc[mt][nt][3] + byv;
            *(float2*)(Cext + (size_t)r0 * DM + col) = o0;
            *(float2*)(Cext + (size_t)(r0 + 8) * DM + col) = o1;
        }
    }
}

// ============================================================
// Flash attention fp16 2-pass: Q split x2, K single, P split x2,
// V single. 128-thr CTAs, BN=32, 2 CTAs/SM.
// smem: Qh 0 (64x272), Ql 17408; stage s @ 34816+s*18944:
//   K +0 (32x272), Vt +8704 (128x80)
// ============================================================
#define AQS 272
#define AVS 80
#define QREG 34816
#define SKV 18944
#define ASMEM (QREG + 2 * SKV)   // 72704

__global__ __launch_bounds__(128, 2) void attn_mma()
{
    extern __shared__ char sm[];
    const uint32_t sb0 = smem_u32(sm);
    const int qt = gridDim.x - 1 - blockIdx.x;
    const int h = blockIdx.y, b = blockIdx.z;
    const int tid = threadIdx.x, lane = tid & 31, w = tid >> 5;
    const int g = lane >> 2, t2 = lane & 3;
    const int a_r = lane & 15;
    const uint32_t a_kb = (lane & 16) ? 16 : 0;
    const int b_n = (lane & 7) + ((lane & 16) ? 8 : 0);
    const uint32_t b_kb = (lane & 8) ? 16 : 0;

    {
        const size_t qbase = (size_t)(b * TT + qt * 64) * DM + h * DH;
#pragma unroll
        for (int j = 0; j < 8; j++) {
            const int n = tid + j * 128;
            const int row = n >> 4, ch = n & 15;
            const size_t gq = qbase + (size_t)row * DM + ch * 8;
            CP16(sb0 + row * AQS + ch * 16, g_qfh + gq);
            CP16(sb0 + 17408 + row * AQS + ch * 16, g_qfl + gq);
        }
    }
    CP_COMMIT();
    CP_WAIT0();
    __syncthreads();

    uint32_t aQh[8][4], aQl[8][4];
#pragma unroll
    for (int kt = 0; kt < 8; kt++) {
        const uint32_t qaddr = sb0 + (w * 16 + a_r) * AQS + kt * 32 + a_kb;
        ldsm_x4(aQh[kt][0], aQh[kt][1], aQh[kt][2], aQh[kt][3], qaddr);
        ldsm_x4(aQl[kt][0], aQl[kt][1], aQl[kt][2], aQl[kt][3], qaddr + 17408);
    }

#define LOADKV(buf, kb) do { \
    const uint32_t kvb_ = sb0 + QREG + (buf) * SKV; \
    const size_t kbase_ = (size_t)(b * TT + (kb) * 32) * DH; \
    const size_t vbase_ = (size_t)b * DH * TT + (size_t)(kb) * 32; \
    _Pragma("unroll") \
    for (int j_ = 0; j_ < 4; j_++) { \
        const int n_ = tid + j_ * 128; \
        const int kr_ = n_ >> 4, kc_ = n_ & 15; \
        CP16(kvb_ + kr_ * AQS + kc_ * 16, g_k + kbase_ + (size_t)kr_ * DH + kc_ * 8); \
        const int vr_ = n_ >> 2, vc_ = n_ & 3; \
        CP16(kvb_ + 8704 + vr_ * AVS + vc_ * 16, g_vt + vbase_ + (size_t)vr_ * TT + vc_ * 8); \
    } \
} while (0)

    const int ntiles = 2 * qt + 2;
    LOADKV(0, 0);
    CP_COMMIT();

    float O[16][4];
#pragma unroll
    for (int i = 0; i < 16; i++)
#pragma unroll
        for (int e = 0; e < 4; e++) O[i][e] = 0.f;
    float m0 = -1e30f, m1 = -1e30f, l0 = 0.f, l1 = 0.f;
    const float sc2 = 0.08838834764831845f * 1.4426950408889634f;
    const int qrow0 = qt * 64 + w * 16 + g;
    const int wrow_max = qt * 64 + w * 16 + 15;

    for (int it = 0; it < ntiles; it++) {
        if (it + 1 < ntiles) { LOADKV((it + 1) & 1, it + 1); CP_COMMIT(); CP_WAIT1(); }
        else                 { CP_WAIT0(); }
        __syncthreads();
        const uint32_t kvb = sb0 + QREG + (it & 1) * SKV;

        if (it * 32 <= wrow_max) {
            // ---- S = Q K^T (2-pass) ----
            float sS[4][4];
#pragma unroll
            for (int i = 0; i < 4; i++)
#pragma unroll
                for (int e = 0; e < 4; e++) sS[i][e] = 0.f;
#pragma unroll
            for (int kt = 0; kt < 8; kt++) {
                uint32_t kb[4][2];
#pragma unroll
                for (int p = 0; p < 2; p++) {
                    const uint32_t kaddr = kvb + (p * 16 + b_n) * AQS + kt * 32 + b_kb;
                    ldsm_x4(kb[2 * p][0], kb[2 * p][1],
                            kb[2 * p + 1][0], kb[2 * p + 1][1], kaddr);
                }
#pragma unroll
                for (int nt = 0; nt < 4; nt++) mma_f16(sS[nt], aQh[kt], kb[nt]);
#pragma unroll
                for (int nt = 0; nt < 4; nt++) mma_f16(sS[nt], aQl[kt], kb[nt]);
            }

            // ---- online softmax (log2 domain) ----
            const int kcol0 = it * 32 + 2 * t2;
            float ml0 = -1e30f, ml1 = -1e30f;
#pragma unroll
            for (int nt = 0; nt < 4; nt++) {
                const int c = kcol0 + nt * 8;
                float s0 = sS[nt][0] * sc2, s1 = sS[nt][1] * sc2;
                float s2 = sS[nt][2] * sc2, s3 = sS[nt][3] * sc2;
                if (c > qrow0)         s0 = -1e30f;
                if (c + 1 > qrow0)     s1 = -1e30f;
                if (c > qrow0 + 8)     s2 = -1e30f;
                if (c + 1 > qrow0 + 8) s3 = -1e30f;
                sS[nt][0] = s0; sS[nt][1] = s1; sS[nt][2] = s2; sS[nt][3] = s3;
                ml0 = fmaxf(ml0, fmaxf(s0, s1));
                ml1 = fmaxf(ml1, fmaxf(s2, s3));
            }
            ml0 = fmaxf(ml0, __shfl_xor_sync(0xffffffffu, ml0, 1));
            ml0 = fmaxf(ml0, __shfl_xor_sync(0xffffffffu, ml0, 2));
            ml1 = fmaxf(ml1, __shfl_xor_sync(0xffffffffu, ml1, 1));
            ml1 = fmaxf(ml1, __shfl_xor_sync(0xffffffffu, ml1, 2));
            const float mn0 = fmaxf(m0, ml0), mn1 = fmaxf(m1, ml1);
            const float al0 = ex2f(m0 - mn0), al1 = ex2f(m1 - mn1);

            float ps0 = 0.f, ps1 = 0.f;
            uint32_t aPh[2][4], aPl[2][4];
#pragma unroll
            for (int u = 0; u < 2; u++) {
                const float p00 = ex2f(sS[2 * u][0] - mn0);
                const float p01 = ex2f(sS[2 * u][1] - mn0);
                const float p02 = ex2f(sS[2 * u][2] - mn1);
                const float p03 = ex2f(sS[2 * u][3] - mn1);
                const float p10 = ex2f(sS[2 * u + 1][0] - mn0);
                const float p11 = ex2f(sS[2 * u + 1][1] - mn0);
                const float p12 = ex2f(sS[2 * u + 1][2] - mn1);
                const float p13 = ex2f(sS[2 * u + 1][3] - mn1);
                ps0 += p00 + p01 + p10 + p11;
                ps1 += p02 + p03 + p12 + p13;
                aPh[u][0] = spkh_hi(p00, p01); aPl[u][0] = spkh_lo(p00, p01);
                aPh[u][1] = spkh_hi(p02, p03); aPl[u][1] = spkh_lo(p02, p03);
                aPh[u][2] = spkh_hi(p10, p11); aPl[u][2] = spkh_lo(p10, p11);
                aPh[u][3] = spkh_hi(p12, p13); aPl[u][3] = spkh_lo(p12, p13);
            }
            ps0 += __shfl_xor_sync(0xffffffffu, ps0, 1);
            ps0 += __shfl_xor_sync(0xffffffffu, ps0, 2);
            ps1 += __shfl_xor_sync(0xffffffffu, ps1, 1);
            ps1 += __shfl_xor_sync(0xffffffffu, ps1, 2);
            l0 = l0 * al0 + ps0;
            l1 = l1 * al1 + ps1;
            m0 = mn0; m1 = mn1;
#pragma unroll
            for (int i = 0; i < 16; i++) {
                O[i][0] *= al0; O[i][1] *= al0;
                O[i][2] *= al1; O[i][3] *= al1;
            }

            // ---- O += P V (2-pass) ----
#pragma unroll
            for (int u = 0; u < 2; u++) {
#pragma unroll
                for (int pp = 0; pp < 4; pp++) {
                    uint32_t vb[4][2];
#pragma unroll
                    for (int pi = 0; pi < 2; pi++) {
                        const int p = 2 * pp + pi;
                        const uint32_t vaddr =
                            kvb + 8704 + (p * 16 + b_n) * AVS + u * 32 + b_kb;
                        ldsm_x4(vb[2 * pi][0], vb[2 * pi][1],
                                vb[2 * pi + 1][0], vb[2 * pi + 1][1], vaddr);
                    }
#pragma unroll
                    for (int q = 0; q < 4; q++) mma_f16(O[4 * pp + q], aPh[u], vb[q]);
#pragma unroll
                    for (int q = 0; q < 4; q++) mma_f16(O[4 * pp + q], aPl[u], vb[q]);
                }
            }
        }
        __syncthreads();
    }

    const float inv0 = 1.0f / l0, inv1 = 1.0f / l1;
    const size_t obase = (size_t)(b * TT + qrow0) * DM + h * DH;
#pragma unroll
    for (int ntd = 0; ntd < 16; ntd++) {
        const int d = ntd * 8 + 2 * t2;
        const float v0 = O[ntd][0] * inv0, v1 = O[ntd][1] * inv0;
        const float v2 = O[ntd][2] * inv1, v3 = O[ntd][3] * inv1;
        *(uint32_t*)&g_chi[obase + d] = splitpk_hi(v0, v1);
        *(uint32_t*)&g_clo[obase + d] = splitpk_lo(v0, v1);
        *(uint32_t*)&g_chi[obase + 8 * DM + d] = splitpk_hi(v2, v3);
        *(uint32_t*)&g_clo[obase + 8 * DM + d] = splitpk_lo(v2, v3);
    }
}

// ============================================================
extern "C" void kernel_launch(void* const* d_in, const int* in_sizes, int n_in,
                              void* d_out, int out_size)
{
    const float* x  = (const float*)d_in[0];
    const float* Wq = (const float*)d_in[2];
    const float* bq = (const float*)d_in[3];
    const float* Wk = (const float*)d_in[4];
    const float* bk = (const float*)d_in[5];
    const float* Wv = (const float*)d_in[6];
    const float* bv = (const float*)d_in[7];
    const float* Wo = (const float*)d_in[8];
    const float* bo = (const float*)d_in[9];
    float* out = (float*)d_out;

    const int gsmem = 2 * STG;
    cudaFuncSetAttribute(tc_gemm_qkv, cudaFuncAttributeMaxDynamicSharedMemorySize, gsmem);
    cudaFuncSetAttribute(tc_gemm_o, cudaFuncAttributeMaxDynamicSharedMemorySize, gsmem);
    cudaFuncSetAttribute(attn_mma, cudaFuncAttributeMaxDynamicSharedMemorySize, ASMEM);

    prep_kernel<<<12800, 256>>>(x, Wq, Wk, Wv, Wo);

    tc_gemm_qkv<<<dim3(18, MROWS / 128), 256, gsmem>>>(bq, bk, bv);

    attn_mma<<<dim3(TT / 64, NH, BBAT), 128, ASMEM>>>();

    tc_gemm_o<<<dim3(16, MROWS / 128), 256, gsmem>>>(bo, out);
}

// round 13
// speedup vs baseline: 1.3850x; 1.1655x over previous
#include <cuda_runtime.h>
#include <cuda_bf16.h>
#include <cuda_fp16.h>
#include <cstdint>

#define BBAT 4
#define TT 2048
#define DM 2048
#define NH 16
#define DH 128
#define MROWS (BBAT * TT)

// ---- scratch (all fp16 now) ----
__device__ __half g_xfh[(size_t)MROWS * DM], g_xfl[(size_t)MROWS * DM];  // x split
__device__ __half g_cfh[(size_t)MROWS * DM], g_cfl[(size_t)MROWS * DM];  // ctx split
__device__ __half g_qfh[(size_t)MROWS * DM], g_qfl[(size_t)MROWS * DM];  // Q split
__device__ __half g_k[(size_t)MROWS * DH];                               // K single
__device__ __half g_vt[(size_t)DH * MROWS];                              // V single, [b][d][t]
__device__ __half g_wq[(size_t)DM * DM];                                 // weights single, [N][K]
__device__ __half g_wk[(size_t)DH * DM];
__device__ __half g_wv[(size_t)DH * DM];
__device__ __half g_wo[(size_t)DM * DM];

// ---- PTX helpers ----
__device__ __forceinline__ uint32_t smem_u32(const void* p) {
    uint32_t a;
    asm("{ .reg .u64 t; cvta.to.shared.u64 t, %1; cvt.u32.u64 %0, t; }" : "=r"(a) : "l"(p));
    return a;
}
#define CP16(s, g) \
    asm volatile("cp.async.cg.shared.global [%0], [%1], 16;" :: "r"(s), "l"(g))
#define CP_COMMIT() asm volatile("cp.async.commit_group;" ::: "memory")
#define CP_WAIT1() asm volatile("cp.async.wait_group 1;" ::: "memory")
#define CP_WAIT0() asm volatile("cp.async.wait_group 0;" ::: "memory")

__device__ __forceinline__ void ldsm_x4(uint32_t& r0, uint32_t& r1, uint32_t& r2,
                                        uint32_t& r3, uint32_t addr) {
    asm volatile("ldmatrix.sync.aligned.m8n8.x4.shared.b16 {%0,%1,%2,%3}, [%4];"
                 : "=r"(r0), "=r"(r1), "=r"(r2), "=r"(r3) : "r"(addr));
}
__device__ __forceinline__ void mma_f16(float* c, const uint32_t* a, const uint32_t* b) {
    asm volatile("mma.sync.aligned.m16n8k16.row.col.f32.f16.f16.f32 "
                 "{%0,%1,%2,%3}, {%4,%5,%6,%7}, {%8,%9}, {%0,%1,%2,%3};"
                 : "+f"(c[0]), "+f"(c[1]), "+f"(c[2]), "+f"(c[3])
                 : "r"(a[0]), "r"(a[1]), "r"(a[2]), "r"(a[3]), "r"(b[0]), "r"(b[1]));
}
__device__ __forceinline__ float ex2f(float x) {
    float y;
    asm("ex2.approx.f32 %0, %1;" : "=f"(y) : "f"(x));
    return y;
}

// ---- fp16 splits ----
__device__ __forceinline__ uint32_t pk2h(__half a, __half b) {
    return (uint32_t)__half_as_ushort(a) | ((uint32_t)__half_as_ushort(b) << 16);
}
__device__ __forceinline__ uint32_t spkh_hi(float a, float b) {
    return pk2h(__float2half_rn(a), __float2half_rn(b));
}
__device__ __forceinline__ uint32_t spkh_lo(float a, float b) {
    __half ha = __float2half_rn(a), hb = __float2half_rn(b);
    return pk2h(__float2half_rn(a - __half2float(ha)),
                __float2half_rn(b - __half2float(hb)));
}

// ============================================================
// Fused prep:
//  [0,4096)      x -> fp16 hi/lo
//  [4096,8192)   Wq -> single fp16 transposed
//  [8192,8448)   Wk
//  [8448,8704)   Wv
//  [8704,12800)  Wo
// ============================================================
__device__ __forceinline__ void do_tsingle_h(const float* __restrict__ W,
                                             __half* dst, int Kd, int Nd, int bx2,
                                             float (*t)[33]) {
    const int xw = Nd / 32;
    const int nb = (bx2 % xw) * 32, kb = (bx2 / xw) * 32;
    const int tx = threadIdx.x & 31, ty = threadIdx.x >> 5;
#pragma unroll
    for (int i = 0; i < 4; i++)
        t[ty + 8 * i][tx] = W[(size_t)(kb + ty + 8 * i) * Nd + nb + tx];
    __syncthreads();
#pragma unroll
    for (int i = 0; i < 4; i++) {
        const int nrow = ty + 8 * i;
        dst[(size_t)(nb + nrow) * Kd + kb + tx] = __float2half_rn(t[tx][nrow]);
    }
}

__global__ __launch_bounds__(256) void prep_kernel(
    const float* __restrict__ x, const float* __restrict__ Wq,
    const float* __restrict__ Wk, const float* __restrict__ Wv,
    const float* __restrict__ Wo)
{
    __shared__ float t[32][33];
    const int bx = blockIdx.x;
    if (bx < 4096) {
        const int n4 = MROWS * DM / 4;
        for (int i = bx * 256 + threadIdx.x; i < n4; i += 4096 * 256) {
            float4 v = ((const float4*)x)[i];
            uint2 FH, FL;
            FH.x = spkh_hi(v.x, v.y); FH.y = spkh_hi(v.z, v.w);
            FL.x = spkh_lo(v.x, v.y); FL.y = spkh_lo(v.z, v.w);
            ((uint2*)g_xfh)[i] = FH;
            ((uint2*)g_xfl)[i] = FL;
        }
    } else if (bx < 8192) {
        do_tsingle_h(Wq, g_wq, DM, DM, bx - 4096, t);
    } else if (bx < 8448) {
        do_tsingle_h(Wk, g_wk, DM, DH, bx - 8192, t);
    } else if (bx < 8704) {
        do_tsingle_h(Wv, g_wv, DM, DH, bx - 8448, t);
    } else {
        do_tsingle_h(Wo, g_wo, DM, DM, bx - 8704, t);
    }
}

// ============================================================
// Unified fp16 2-pass GEMM core (A split hi/lo x B single).
// stage layout: Ah@0, Al@10240, B@20480 (rows 128x80B). STG=30720.
// ============================================================
#define STG 30720

// mode: 0 = QKV (bx<16 Q, bx==16 K, bx==17 V-transposed)
//       1 = O projection (fp32 out)
__global__ __launch_bounds__(256, 2) void tc_gemm(
    const float* __restrict__ b0, const float* __restrict__ b1,
    const float* __restrict__ b2, float* __restrict__ Cext, int mode)
{
    extern __shared__ char sm[];
    const uint32_t sbase = smem_u32(sm);
    const int tid = threadIdx.x;
    const int lane = tid & 31, warp = tid >> 5;
    const int wm = warp & 3, wn = warp >> 2;
    const int bx = blockIdx.x;
    const int rowBase = blockIdx.y * 128;

    const __half* Ahi = mode ? g_cfh : g_xfh;
    const __half* Alo = mode ? g_cfl : g_xfl;
    const __half* B;
    int wRow0;
    if (mode) { B = g_wo; wRow0 = bx * 128; }
    else if (bx < 16)  { B = g_wq; wRow0 = bx * 128; }
    else if (bx == 16) { B = g_wk; wRow0 = 0; }
    else               { B = g_wv; wRow0 = 0; }

    float acc[2][8][4];
#pragma unroll
    for (int mt = 0; mt < 2; mt++)
#pragma unroll
        for (int nt = 0; nt < 8; nt++)
#pragma unroll
            for (int e = 0; e < 4; e++) acc[mt][nt][e] = 0.f;

    const int lr = tid >> 2, lc = tid & 3;
    const int a_r = lane & 15;
    const uint32_t a_kb = (lane & 16) ? 16 : 0;
    const int b_n = (lane & 7) + ((lane & 16) ? 8 : 0);
    const uint32_t b_kb = (lane & 8) ? 16 : 0;
    const int g = lane >> 2, t2 = lane & 3;

#define LOAD_STAGE(buf, k0) do { \
    const uint32_t sb_ = sbase + (buf) * STG; \
    _Pragma("unroll") \
    for (int h_ = 0; h_ < 2; h_++) { \
        const int r_ = lr + h_ * 64; \
        const uint32_t so_ = r_ * 80 + lc * 16; \
        const size_t ga_ = (size_t)(rowBase + r_) * DM + (k0) + lc * 8; \
        const size_t gb_ = (size_t)(wRow0 + r_) * DM + (k0) + lc * 8; \
        CP16(sb_ + so_, Ahi + ga_); \
        CP16(sb_ + 10240 + so_, Alo + ga_); \
        CP16(sb_ + 20480 + so_, B + gb_); \
    } \
} while (0)

    LOAD_STAGE(0, 0);
    CP_COMMIT();

    const int ITERS = DM / 32;
    for (int s = 0; s < ITERS; s++) {
        if (s + 1 < ITERS) { LOAD_STAGE((s + 1) & 1, (s + 1) * 32); CP_COMMIT(); CP_WAIT1(); }
        else               { CP_WAIT0(); }
        __syncthreads();

        const uint32_t sb = sbase + (s & 1) * STG;
#pragma unroll
        for (int ks = 0; ks < 2; ks++) {
            const uint32_t kso = ks * 32;
            uint32_t ah[2][4], al[2][4], bb[8][2];
#pragma unroll
            for (int mt = 0; mt < 2; mt++) {
                const uint32_t addr = sb + (wm * 32 + mt * 16 + a_r) * 80 + kso + a_kb;
                ldsm_x4(ah[mt][0], ah[mt][1], ah[mt][2], ah[mt][3], addr);
                ldsm_x4(al[mt][0], al[mt][1], al[mt][2], al[mt][3], addr + 10240);
            }
#pragma unroll
            for (int p = 0; p < 4; p++) {
                const uint32_t addr = sb + 20480 + (wn * 64 + p * 16 + b_n) * 80 + kso + b_kb;
                ldsm_x4(bb[p * 2][0], bb[p * 2][1], bb[p * 2 + 1][0], bb[p * 2 + 1][1], addr);
            }
#pragma unroll
            for (int mt = 0; mt < 2; mt++)
#pragma unroll
                for (int nt = 0; nt < 8; nt++)
                    mma_f16(acc[mt][nt], ah[mt], bb[nt]);
#pragma unroll
            for (int mt = 0; mt < 2; mt++)
#pragma unroll
                for (int nt = 0; nt < 8; nt++)
                    mma_f16(acc[mt][nt], al[mt], bb[nt]);
        }
        __syncthreads();
    }

    if (mode) {
        // O projection: fp32 out + bias b0
#pragma unroll
        for (int mt = 0; mt < 2; mt++) {
            const int r0 = rowBase + wm * 32 + mt * 16 + g;
#pragma unroll
            for (int nt = 0; nt < 8; nt++) {
                const int col = bx * 128 + wn * 64 + nt * 8 + t2 * 2;
                const float bxv = b0[col], byv = b0[col + 1];
                float2 o0, o1;
                o0.x = acc[mt][nt][0] + bxv; o0.y = acc[mt][nt][1] + byv;
                o1.x = acc[mt][nt][2] + bxv; o1.y = acc[mt][nt][3] + byv;
                *(float2*)(Cext + (size_t)r0 * DM + col) = o0;
                *(float2*)(Cext + (size_t)(r0 + 8) * DM + col) = o1;
            }
        }
    } else if (bx < 16) {
        // Q: fp16 split out, bias b0
#pragma unroll
        for (int mt = 0; mt < 2; mt++) {
            const int r0 = rowBase + wm * 32 + mt * 16 + g;
#pragma unroll
            for (int nt = 0; nt < 8; nt++) {
                const int col = bx * 128 + wn * 64 + nt * 8 + t2 * 2;
                const float bxv = b0[col], byv = b0[col + 1];
                const float v0 = acc[mt][nt][0] + bxv, v1 = acc[mt][nt][1] + byv;
                const float v2 = acc[mt][nt][2] + bxv, v3 = acc[mt][nt][3] + byv;
                *(uint32_t*)&g_qfh[(size_t)r0 * DM + col] = spkh_hi(v0, v1);
                *(uint32_t*)&g_qfl[(size_t)r0 * DM + col] = spkh_lo(v0, v1);
                *(uint32_t*)&g_qfh[(size_t)(r0 + 8) * DM + col] = spkh_hi(v2, v3);
                *(uint32_t*)&g_qfl[(size_t)(r0 + 8) * DM + col] = spkh_lo(v2, v3);
            }
        }
    } else if (bx == 16) {
        // K: single fp16, stride DH, bias b1
#pragma unroll
        for (int mt = 0; mt < 2; mt++) {
            const int r0 = rowBase + wm * 32 + mt * 16 + g;
#pragma unroll
            for (int nt = 0; nt < 8; nt++) {
                const int col = wn * 64 + nt * 8 + t2 * 2;
                const float bxv = b1[col], byv = b1[col + 1];
                const float v0 = acc[mt][nt][0] + bxv, v1 = acc[mt][nt][1] + byv;
                const float v2 = acc[mt][nt][2] + bxv, v3 = acc[mt][nt][3] + byv;
                *(uint32_t*)&g_k[(size_t)r0 * DH + col] = spkh_hi(v0, v1);
                *(uint32_t*)&g_k[(size_t)(r0 + 8) * DH + col] = spkh_hi(v2, v3);
            }
        }
    } else {
        // V: single fp16, transposed [b][d][t], bias b2
#pragma unroll
        for (int mt = 0; mt < 2; mt++) {
            const int r0 = rowBase + wm * 32 + mt * 16 + g;
            const int bidx = r0 >> 11;
            const int trow = r0 & (TT - 1);
#pragma unroll
            for (int nt = 0; nt < 8; nt++) {
                const int col = wn * 64 + nt * 8 + t2 * 2;
                const float bxv = b2[col], byv = b2[col + 1];
                const float v0 = acc[mt][nt][0] + bxv, v1 = acc[mt][nt][1] + byv;
                const float v2 = acc[mt][nt][2] + bxv, v3 = acc[mt][nt][3] + byv;
                const size_t base0 = ((size_t)bidx * DH + col) * TT + trow;
                g_vt[base0]          = __float2half_rn(v0);
                g_vt[base0 + TT]     = __float2half_rn(v1);
                g_vt[base0 + 8]      = __float2half_rn(v2);
                g_vt[base0 + TT + 8] = __float2half_rn(v3);
            }
        }
    }
}

// ============================================================
// Flash attention fp16 2-pass (validated R12); ctx out -> fp16 split.
// smem: Qh 0 (64x272), Ql 17408; stage s @ 34816+s*18944:
//   K +0 (32x272), Vt +8704 (128x80)
// ============================================================
#define AQS 272
#define AVS 80
#define QREG 34816
#define SKV 18944
#define ASMEM (QREG + 2 * SKV)   // 72704

__global__ __launch_bounds__(128, 2) void attn_mma()
{
    extern __shared__ char sm[];
    const uint32_t sb0 = smem_u32(sm);
    const int qt = gridDim.x - 1 - blockIdx.x;
    const int h = blockIdx.y, b = blockIdx.z;
    const int tid = threadIdx.x, lane = tid & 31, w = tid >> 5;
    const int g = lane >> 2, t2 = lane & 3;
    const int a_r = lane & 15;
    const uint32_t a_kb = (lane & 16) ? 16 : 0;
    const int b_n = (lane & 7) + ((lane & 16) ? 8 : 0);
    const uint32_t b_kb = (lane & 8) ? 16 : 0;

    {
        const size_t qbase = (size_t)(b * TT + qt * 64) * DM + h * DH;
#pragma unroll
        for (int j = 0; j < 8; j++) {
            const int n = tid + j * 128;
            const int row = n >> 4, ch = n & 15;
            const size_t gq = qbase + (size_t)row * DM + ch * 8;
            CP16(sb0 + row * AQS + ch * 16, g_qfh + gq);
            CP16(sb0 + 17408 + row * AQS + ch * 16, g_qfl + gq);
        }
    }
    CP_COMMIT();
    CP_WAIT0();
    __syncthreads();

    uint32_t aQh[8][4], aQl[8][4];
#pragma unroll
    for (int kt = 0; kt < 8; kt++) {
        const uint32_t qaddr = sb0 + (w * 16 + a_r) * AQS + kt * 32 + a_kb;
        ldsm_x4(aQh[kt][0], aQh[kt][1], aQh[kt][2], aQh[kt][3], qaddr);
        ldsm_x4(aQl[kt][0], aQl[kt][1], aQl[kt][2], aQl[kt][3], qaddr + 17408);
    }

#define LOADKV(buf, kb) do { \
    const uint32_t kvb_ = sb0 + QREG + (buf) * SKV; \
    const size_t kbase_ = (size_t)(b * TT + (kb) * 32) * DH; \
    const size_t vbase_ = (size_t)b * DH * TT + (size_t)(kb) * 32; \
    _Pragma("unroll") \
    for (int j_ = 0; j_ < 4; j_++) { \
        const int n_ = tid + j_ * 128; \
        const int kr_ = n_ >> 4, kc_ = n_ & 15; \
        CP16(kvb_ + kr_ * AQS + kc_ * 16, g_k + kbase_ + (size_t)kr_ * DH + kc_ * 8); \
        const int vr_ = n_ >> 2, vc_ = n_ & 3; \
        CP16(kvb_ + 8704 + vr_ * AVS + vc_ * 16, g_vt + vbase_ + (size_t)vr_ * TT + vc_ * 8); \
    } \
} while (0)

    const int ntiles = 2 * qt + 2;
    LOADKV(0, 0);
    CP_COMMIT();

    float O[16][4];
#pragma unroll
    for (int i = 0; i < 16; i++)
#pragma unroll
        for (int e = 0; e < 4; e++) O[i][e] = 0.f;
    float m0 = -1e30f, m1 = -1e30f, l0 = 0.f, l1 = 0.f;
    const float sc2 = 0.08838834764831845f * 1.4426950408889634f;
    const int qrow0 = qt * 64 + w * 16 + g;
    const int wrow_max = qt * 64 + w * 16 + 15;

    for (int it = 0; it < ntiles; it++) {
        if (it + 1 < ntiles) { LOADKV((it + 1) & 1, it + 1); CP_COMMIT(); CP_WAIT1(); }
        else                 { CP_WAIT0(); }
        __syncthreads();
        const uint32_t kvb = sb0 + QREG + (it & 1) * SKV;

        if (it * 32 <= wrow_max) {
            // ---- S = Q K^T (2-pass) ----
            float sS[4][4];
#pragma unroll
            for (int i = 0; i < 4; i++)
#pragma unroll
                for (int e = 0; e < 4; e++) sS[i][e] = 0.f;
#pragma unroll
            for (int kt = 0; kt < 8; kt++) {
                uint32_t kb[4][2];
#pragma unroll
                for (int p = 0; p < 2; p++) {
                    const uint32_t kaddr = kvb + (p * 16 + b_n) * AQS + kt * 32 + b_kb;
                    ldsm_x4(kb[2 * p][0], kb[2 * p][1],
                            kb[2 * p + 1][0], kb[2 * p + 1][1], kaddr);
                }
#pragma unroll
                for (int nt = 0; nt < 4; nt++) mma_f16(sS[nt], aQh[kt], kb[nt]);
#pragma unroll
                for (int nt = 0; nt < 4; nt++) mma_f16(sS[nt], aQl[kt], kb[nt]);
            }

            // ---- online softmax (log2 domain) ----
            const int kcol0 = it * 32 + 2 * t2;
            float ml0 = -1e30f, ml1 = -1e30f;
#pragma unroll
            for (int nt = 0; nt < 4; nt++) {
                const int c = kcol0 + nt * 8;
                float s0 = sS[nt][0] * sc2, s1 = sS[nt][1] * sc2;
                float s2 = sS[nt][2] * sc2, s3 = sS[nt][3] * sc2;
                if (c > qrow0)         s0 = -1e30f;
                if (c + 1 > qrow0)     s1 = -1e30f;
                if (c > qrow0 + 8)     s2 = -1e30f;
                if (c + 1 > qrow0 + 8) s3 = -1e30f;
                sS[nt][0] = s0; sS[nt][1] = s1; sS[nt][2] = s2; sS[nt][3] = s3;
                ml0 = fmaxf(ml0, fmaxf(s0, s1));
                ml1 = fmaxf(ml1, fmaxf(s2, s3));
            }
            ml0 = fmaxf(ml0, __shfl_xor_sync(0xffffffffu, ml0, 1));
            ml0 = fmaxf(ml0, __shfl_xor_sync(0xffffffffu, ml0, 2));
            ml1 = fmaxf(ml1, __shfl_xor_sync(0xffffffffu, ml1, 1));
            ml1 = fmaxf(ml1, __shfl_xor_sync(0xffffffffu, ml1, 2));
            const float mn0 = fmaxf(m0, ml0), mn1 = fmaxf(m1, ml1);
            const float al0 = ex2f(m0 - mn0), al1 = ex2f(m1 - mn1);

            float ps0 = 0.f, ps1 = 0.f;
            uint32_t aPh[2][4], aPl[2][4];
#pragma unroll
            for (int u = 0; u < 2; u++) {
                const float p00 = ex2f(sS[2 * u][0] - mn0);
                const float p01 = ex2f(sS[2 * u][1] - mn0);
                const float p02 = ex2f(sS[2 * u][2] - mn1);
                const float p03 = ex2f(sS[2 * u][3] - mn1);
                const float p10 = ex2f(sS[2 * u + 1][0] - mn0);
                const float p11 = ex2f(sS[2 * u + 1][1] - mn0);
                const float p12 = ex2f(sS[2 * u + 1][2] - mn1);
                const float p13 = ex2f(sS[2 * u + 1][3] - mn1);
                ps0 += p00 + p01 + p10 + p11;
                ps1 += p02 + p03 + p12 + p13;
                aPh[u][0] = spkh_hi(p00, p01); aPl[u][0] = spkh_lo(p00, p01);
                aPh[u][1] = spkh_hi(p02, p03); aPl[u][1] = spkh_lo(p02, p03);
                aPh[u][2] = spkh_hi(p10, p11); aPl[u][2] = spkh_lo(p10, p11);
                aPh[u][3] = spkh_hi(p12, p13); aPl[u][3] = spkh_lo(p12, p13);
            }
            ps0 += __shfl_xor_sync(0xffffffffu, ps0, 1);
            ps0 += __shfl_xor_sync(0xffffffffu, ps0, 2);
            ps1 += __shfl_xor_sync(0xffffffffu, ps1, 1);
            ps1 += __shfl_xor_sync(0xffffffffu, ps1, 2);
            l0 = l0 * al0 + ps0;
            l1 = l1 * al1 + ps1;
            m0 = mn0; m1 = mn1;
#pragma unroll
            for (int i = 0; i < 16; i++) {
                O[i][0] *= al0; O[i][1] *= al0;
                O[i][2] *= al1; O[i][3] *= al1;
            }

            // ---- O += P V (2-pass) ----
#pragma unroll
            for (int u = 0; u < 2; u++) {
#pragma unroll
                for (int pp = 0; pp < 4; pp++) {
                    uint32_t vb[4][2];
#pragma unroll
                    for (int pi = 0; pi < 2; pi++) {
                        const int p = 2 * pp + pi;
                        const uint32_t vaddr =
                            kvb + 8704 + (p * 16 + b_n) * AVS + u * 32 + b_kb;
                        ldsm_x4(vb[2 * pi][0], vb[2 * pi][1],
                                vb[2 * pi + 1][0], vb[2 * pi + 1][1], vaddr);
                    }
#pragma unroll
                    for (int q = 0; q < 4; q++) mma_f16(O[4 * pp + q], aPh[u], vb[q]);
#pragma unroll
                    for (int q = 0; q < 4; q++) mma_f16(O[4 * pp + q], aPl[u], vb[q]);
                }
            }
        }
        __syncthreads();
    }

    const float inv0 = 1.0f / l0, inv1 = 1.0f / l1;
    const size_t obase = (size_t)(b * TT + qrow0) * DM + h * DH;
#pragma unroll
    for (int ntd = 0; ntd < 16; ntd++) {
        const int d = ntd * 8 + 2 * t2;
        const float v0 = O[ntd][0] * inv0, v1 = O[ntd][1] * inv0;
        const float v2 = O[ntd][2] * inv1, v3 = O[ntd][3] * inv1;
        *(uint32_t*)&g_cfh[obase + d] = spkh_hi(v0, v1);
        *(uint32_t*)&g_cfl[obase + d] = spkh_lo(v0, v1);
        *(uint32_t*)&g_cfh[obase + 8 * DM + d] = spkh_hi(v2, v3);
        *(uint32_t*)&g_cfl[obase + 8 * DM + d] = spkh_lo(v2, v3);
    }
}

// ============================================================
extern "C" void kernel_launch(void* const* d_in, const int* in_sizes, int n_in,
                              void* d_out, int out_size)
{
    const float* x  = (const float*)d_in[0];
    const float* Wq = (const float*)d_in[2];
    const float* bq = (const float*)d_in[3];
    const float* Wk = (const float*)d_in[4];
    const float* bk = (const float*)d_in[5];
    const float* Wv = (const float*)d_in[6];
    const float* bv = (const float*)d_in[7];
    const float* Wo = (const float*)d_in[8];
    const float* bo = (const float*)d_in[9];
    float* out = (float*)d_out;

    const int gsmem = 2 * STG;   // 61440
    cudaFuncSetAttribute(tc_gemm, cudaFuncAttributeMaxDynamicSharedMemorySize, gsmem);
    cudaFuncSetAttribute(attn_mma, cudaFuncAttributeMaxDynamicSharedMemorySize, ASMEM);

    prep_kernel<<<12800, 256>>>(x, Wq, Wk, Wv, Wo);

    // fused QKV projection (all fp16 2-pass)
    tc_gemm<<<dim3(18, MROWS / 128), 256, gsmem>>>(bq, bk, bv, nullptr, 0);

    attn_mma<<<dim3(TT / 64, NH, BBAT), 128, ASMEM>>>();

    // O projection (fp16 2-pass, fp32 out)
    tc_gemm<<<dim3(16, MROWS / 128), 256, gsmem>>>(bo, nullptr, nullptr, out, 1);
}

// round 14
// speedup vs baseline: 1.3953x; 1.0074x over previous
#include <cuda_runtime.h>
#include <cuda_bf16.h>
#include <cuda_fp16.h>
#include <cstdint>

#define BBAT 4
#define TT 2048
#define DM 2048
#define NH 16
#define DH 128
#define MROWS (BBAT * TT)

// ---- scratch (all fp16) ----
__device__ __half g_xfh[(size_t)MROWS * DM], g_xfl[(size_t)MROWS * DM];
__device__ __half g_cfh[(size_t)MROWS * DM], g_cfl[(size_t)MROWS * DM];
__device__ __half g_qfh[(size_t)MROWS * DM], g_qfl[(size_t)MROWS * DM];
__device__ __half g_k[(size_t)MROWS * DH];
__device__ __half g_vt[(size_t)DH * MROWS];
__device__ __half g_wq[(size_t)DM * DM];
__device__ __half g_wk[(size_t)DH * DM];
__device__ __half g_wv[(size_t)DH * DM];
__device__ __half g_wo[(size_t)DM * DM];

// ---- PTX helpers ----
__device__ __forceinline__ uint32_t smem_u32(const void* p) {
    uint32_t a;
    asm("{ .reg .u64 t; cvta.to.shared.u64 t, %1; cvt.u32.u64 %0, t; }" : "=r"(a) : "l"(p));
    return a;
}
#define CP16(s, g) \
    asm volatile("cp.async.cg.shared.global [%0], [%1], 16;" :: "r"(s), "l"(g))
#define CP_COMMIT() asm volatile("cp.async.commit_group;" ::: "memory")
#define CP_WAIT1() asm volatile("cp.async.wait_group 1;" ::: "memory")
#define CP_WAIT0() asm volatile("cp.async.wait_group 0;" ::: "memory")

__device__ __forceinline__ void ldsm_x4(uint32_t& r0, uint32_t& r1, uint32_t& r2,
                                        uint32_t& r3, uint32_t addr) {
    asm volatile("ldmatrix.sync.aligned.m8n8.x4.shared.b16 {%0,%1,%2,%3}, [%4];"
                 : "=r"(r0), "=r"(r1), "=r"(r2), "=r"(r3) : "r"(addr));
}
__device__ __forceinline__ void mma_f16(float* c, const uint32_t* a, const uint32_t* b) {
    asm volatile("mma.sync.aligned.m16n8k16.row.col.f32.f16.f16.f32 "
                 "{%0,%1,%2,%3}, {%4,%5,%6,%7}, {%8,%9}, {%0,%1,%2,%3};"
                 : "+f"(c[0]), "+f"(c[1]), "+f"(c[2]), "+f"(c[3])
                 : "r"(a[0]), "r"(a[1]), "r"(a[2]), "r"(a[3]), "r"(b[0]), "r"(b[1]));
}
__device__ __forceinline__ float ex2f(float x) {
    float y;
    asm("ex2.approx.f32 %0, %1;" : "=f"(y) : "f"(x));
    return y;
}

// ---- fp16 splits ----
__device__ __forceinline__ uint32_t pk2h(__half a, __half b) {
    return (uint32_t)__half_as_ushort(a) | ((uint32_t)__half_as_ushort(b) << 16);
}
__device__ __forceinline__ uint32_t spkh_hi(float a, float b) {
    return pk2h(__float2half_rn(a), __float2half_rn(b));
}
__device__ __forceinline__ uint32_t spkh_lo(float a, float b) {
    __half ha = __float2half_rn(a), hb = __float2half_rn(b);
    return pk2h(__float2half_rn(a - __half2float(ha)),
                __float2half_rn(b - __half2float(hb)));
}

// ============================================================
// Fused prep (unchanged)
// ============================================================
__device__ __forceinline__ void do_tsingle_h(const float* __restrict__ W,
                                             __half* dst, int Kd, int Nd, int bx2,
                                             float (*t)[33]) {
    const int xw = Nd / 32;
    const int nb = (bx2 % xw) * 32, kb = (bx2 / xw) * 32;
    const int tx = threadIdx.x & 31, ty = threadIdx.x >> 5;
#pragma unroll
    for (int i = 0; i < 4; i++)
        t[ty + 8 * i][tx] = W[(size_t)(kb + ty + 8 * i) * Nd + nb + tx];
    __syncthreads();
#pragma unroll
    for (int i = 0; i < 4; i++) {
        const int nrow = ty + 8 * i;
        dst[(size_t)(nb + nrow) * Kd + kb + tx] = __float2half_rn(t[tx][nrow]);
    }
}

__global__ __launch_bounds__(256) void prep_kernel(
    const float* __restrict__ x, const float* __restrict__ Wq,
    const float* __restrict__ Wk, const float* __restrict__ Wv,
    const float* __restrict__ Wo)
{
    __shared__ float t[32][33];
    const int bx = blockIdx.x;
    if (bx < 4096) {
        const int n4 = MROWS * DM / 4;
        for (int i = bx * 256 + threadIdx.x; i < n4; i += 4096 * 256) {
            float4 v = ((const float4*)x)[i];
            uint2 FH, FL;
            FH.x = spkh_hi(v.x, v.y); FH.y = spkh_hi(v.z, v.w);
            FL.x = spkh_lo(v.x, v.y); FL.y = spkh_lo(v.z, v.w);
            ((uint2*)g_xfh)[i] = FH;
            ((uint2*)g_xfl)[i] = FL;
        }
    } else if (bx < 8192) {
        do_tsingle_h(Wq, g_wq, DM, DM, bx - 4096, t);
    } else if (bx < 8448) {
        do_tsingle_h(Wk, g_wk, DM, DH, bx - 8192, t);
    } else if (bx < 8704) {
        do_tsingle_h(Wv, g_wv, DM, DH, bx - 8448, t);
    } else {
        do_tsingle_h(Wo, g_wo, DM, DM, bx - 8704, t);
    }
}

// ============================================================
// fp16 2-pass GEMM, 3-stage cp.async, ONE barrier per iteration.
// stage: Ah@0, Al@10240, B@20480 (rows 128x80B). STG=30720, 3 stages.
// ============================================================
#define STG 30720

__global__ __launch_bounds__(256, 2) void tc_gemm(
    const float* __restrict__ b0, const float* __restrict__ b1,
    const float* __restrict__ b2, float* __restrict__ Cext, int mode)
{
    extern __shared__ char sm[];
    const uint32_t sbase = smem_u32(sm);
    const int tid = threadIdx.x;
    const int lane = tid & 31, warp = tid >> 5;
    const int wm = warp & 3, wn = warp >> 2;
    const int bx = blockIdx.x;
    const int rowBase = blockIdx.y * 128;

    const __half* Ahi = mode ? g_cfh : g_xfh;
    const __half* Alo = mode ? g_cfl : g_xfl;
    const __half* B;
    int wRow0;
    if (mode) { B = g_wo; wRow0 = bx * 128; }
    else if (bx < 16)  { B = g_wq; wRow0 = bx * 128; }
    else if (bx == 16) { B = g_wk; wRow0 = 0; }
    else               { B = g_wv; wRow0 = 0; }

    float acc[2][8][4];
#pragma unroll
    for (int mt = 0; mt < 2; mt++)
#pragma unroll
        for (int nt = 0; nt < 8; nt++)
#pragma unroll
            for (int e = 0; e < 4; e++) acc[mt][nt][e] = 0.f;

    const int lr = tid >> 2, lc = tid & 3;
    const int a_r = lane & 15;
    const uint32_t a_kb = (lane & 16) ? 16 : 0;
    const int b_n = (lane & 7) + ((lane & 16) ? 8 : 0);
    const uint32_t b_kb = (lane & 8) ? 16 : 0;
    const int g = lane >> 2, t2 = lane & 3;

#define LOAD_STAGE(buf, k0) do { \
    const uint32_t sb_ = sbase + (buf) * STG; \
    _Pragma("unroll") \
    for (int h_ = 0; h_ < 2; h_++) { \
        const int r_ = lr + h_ * 64; \
        const uint32_t so_ = r_ * 80 + lc * 16; \
        const size_t ga_ = (size_t)(rowBase + r_) * DM + (k0) + lc * 8; \
        const size_t gb_ = (size_t)(wRow0 + r_) * DM + (k0) + lc * 8; \
        CP16(sb_ + so_, Ahi + ga_); \
        CP16(sb_ + 10240 + so_, Alo + ga_); \
        CP16(sb_ + 20480 + so_, B + gb_); \
    } \
} while (0)

    // prologue: stages 0,1
    LOAD_STAGE(0, 0);
    CP_COMMIT();
    LOAD_STAGE(1, 32);
    CP_COMMIT();

    const int ITERS = DM / 32;   // 64
    int buf = 0;                  // s % 3
    for (int s = 0; s < ITERS; s++) {
        if (s + 1 < ITERS) CP_WAIT1();   // stage s complete
        else               CP_WAIT0();
        __syncthreads();                  // all warps done reading stage s-1 (== s+2 mod 3)
        if (s + 2 < ITERS) {
            const int nb = (buf + 2 >= 3) ? buf - 1 : buf + 2;
            LOAD_STAGE(nb, (s + 2) * 32);
            CP_COMMIT();
        }

        const uint32_t sb = sbase + buf * STG;
#pragma unroll
        for (int ks = 0; ks < 2; ks++) {
            const uint32_t kso = ks * 32;
            uint32_t ah[2][4], al[2][4], bb[8][2];
#pragma unroll
            for (int mt = 0; mt < 2; mt++) {
                const uint32_t addr = sb + (wm * 32 + mt * 16 + a_r) * 80 + kso + a_kb;
                ldsm_x4(ah[mt][0], ah[mt][1], ah[mt][2], ah[mt][3], addr);
                ldsm_x4(al[mt][0], al[mt][1], al[mt][2], al[mt][3], addr + 10240);
            }
#pragma unroll
            for (int p = 0; p < 4; p++) {
                const uint32_t addr = sb + 20480 + (wn * 64 + p * 16 + b_n) * 80 + kso + b_kb;
                ldsm_x4(bb[p * 2][0], bb[p * 2][1], bb[p * 2 + 1][0], bb[p * 2 + 1][1], addr);
            }
#pragma unroll
            for (int mt = 0; mt < 2; mt++)
#pragma unroll
                for (int nt = 0; nt < 8; nt++)
                    mma_f16(acc[mt][nt], ah[mt], bb[nt]);
#pragma unroll
            for (int mt = 0; mt < 2; mt++)
#pragma unroll
                for (int nt = 0; nt < 8; nt++)
                    mma_f16(acc[mt][nt], al[mt], bb[nt]);
        }
        buf = (buf == 2) ? 0 : buf + 1;
    }

    if (mode) {
#pragma unroll
        for (int mt = 0; mt < 2; mt++) {
            const int r0 = rowBase + wm * 32 + mt * 16 + g;
#pragma unroll
            for (int nt = 0; nt < 8; nt++) {
                const int col = bx * 128 + wn * 64 + nt * 8 + t2 * 2;
                const float bxv = b0[col], byv = b0[col + 1];
                float2 o0, o1;
                o0.x = acc[mt][nt][0] + bxv; o0.y = acc[mt][nt][1] + byv;
                o1.x = acc[mt][nt][2] + bxv; o1.y = acc[mt][nt][3] + byv;
                *(float2*)(Cext + (size_t)r0 * DM + col) = o0;
                *(float2*)(Cext + (size_t)(r0 + 8) * DM + col) = o1;
            }
        }
    } else if (bx < 16) {
#pragma unroll
        for (int mt = 0; mt < 2; mt++) {
            const int r0 = rowBase + wm * 32 + mt * 16 + g;
#pragma unroll
            for (int nt = 0; nt < 8; nt++) {
                const int col = bx * 128 + wn * 64 + nt * 8 + t2 * 2;
                const float bxv = b0[col], byv = b0[col + 1];
                const float v0 = acc[mt][nt][0] + bxv, v1 = acc[mt][nt][1] + byv;
                const float v2 = acc[mt][nt][2] + bxv, v3 = acc[mt][nt][3] + byv;
                *(uint32_t*)&g_qfh[(size_t)r0 * DM + col] = spkh_hi(v0, v1);
                *(uint32_t*)&g_qfl[(size_t)r0 * DM + col] = spkh_lo(v0, v1);
                *(uint32_t*)&g_qfh[(size_t)(r0 + 8) * DM + col] = spkh_hi(v2, v3);
                *(uint32_t*)&g_qfl[(size_t)(r0 + 8) * DM + col] = spkh_lo(v2, v3);
            }
        }
    } else if (bx == 16) {
#pragma unroll
        for (int mt = 0; mt < 2; mt++) {
            const int r0 = rowBase + wm * 32 + mt * 16 + g;
#pragma unroll
            for (int nt = 0; nt < 8; nt++) {
                const int col = wn * 64 + nt * 8 + t2 * 2;
                const float bxv = b1[col], byv = b1[col + 1];
                const float v0 = acc[mt][nt][0] + bxv, v1 = acc[mt][nt][1] + byv;
                const float v2 = acc[mt][nt][2] + bxv, v3 = acc[mt][nt][3] + byv;
                *(uint32_t*)&g_k[(size_t)r0 * DH + col] = spkh_hi(v0, v1);
                *(uint32_t*)&g_k[(size_t)(r0 + 8) * DH + col] = spkh_hi(v2, v3);
            }
        }
    } else {
#pragma unroll
        for (int mt = 0; mt < 2; mt++) {
            const int r0 = rowBase + wm * 32 + mt * 16 + g;
            const int bidx = r0 >> 11;
            const int trow = r0 & (TT - 1);
#pragma unroll
            for (int nt = 0; nt < 8; nt++) {
                const int col = wn * 64 + nt * 8 + t2 * 2;
                const float bxv = b2[col], byv = b2[col + 1];
                const float v0 = acc[mt][nt][0] + bxv, v1 = acc[mt][nt][1] + byv;
                const float v2 = acc[mt][nt][2] + bxv, v3 = acc[mt][nt][3] + byv;
                const size_t base0 = ((size_t)bidx * DH + col) * TT + trow;
                g_vt[base0]          = __float2half_rn(v0);
                g_vt[base0 + TT]     = __float2half_rn(v1);
                g_vt[base0 + 8]      = __float2half_rn(v2);
                g_vt[base0 + TT + 8] = __float2half_rn(v3);
            }
        }
    }
}

// ============================================================
// Flash attention fp16 2-pass, 3-stage KV pipeline, ONE barrier/iter.
// smem: Qh 0 (64x272), Ql 17408; stage s @ 34816+s*18944:
//   K +0 (32x272), Vt +8704 (128x80)
// ============================================================
#define AQS 272
#define AVS 80
#define QREG 34816
#define SKV 18944
#define ASMEM (QREG + 3 * SKV)   // 91648

__global__ __launch_bounds__(128, 2) void attn_mma()
{
    extern __shared__ char sm[];
    const uint32_t sb0 = smem_u32(sm);
    const int qt = gridDim.x - 1 - blockIdx.x;
    const int h = blockIdx.y, b = blockIdx.z;
    const int tid = threadIdx.x, lane = tid & 31, w = tid >> 5;
    const int g = lane >> 2, t2 = lane & 3;
    const int a_r = lane & 15;
    const uint32_t a_kb = (lane & 16) ? 16 : 0;
    const int b_n = (lane & 7) + ((lane & 16) ? 8 : 0);
    const uint32_t b_kb = (lane & 8) ? 16 : 0;

    {
        const size_t qbase = (size_t)(b * TT + qt * 64) * DM + h * DH;
#pragma unroll
        for (int j = 0; j < 8; j++) {
            const int n = tid + j * 128;
            const int row = n >> 4, ch = n & 15;
            const size_t gq = qbase + (size_t)row * DM + ch * 8;
            CP16(sb0 + row * AQS + ch * 16, g_qfh + gq);
            CP16(sb0 + 17408 + row * AQS + ch * 16, g_qfl + gq);
        }
    }
    CP_COMMIT();
    CP_WAIT0();
    __syncthreads();

    uint32_t aQh[8][4], aQl[8][4];
#pragma unroll
    for (int kt = 0; kt < 8; kt++) {
        const uint32_t qaddr = sb0 + (w * 16 + a_r) * AQS + kt * 32 + a_kb;
        ldsm_x4(aQh[kt][0], aQh[kt][1], aQh[kt][2], aQh[kt][3], qaddr);
        ldsm_x4(aQl[kt][0], aQl[kt][1], aQl[kt][2], aQl[kt][3], qaddr + 17408);
    }

#define LOADKV(buf, kb) do { \
    const uint32_t kvb_ = sb0 + QREG + (buf) * SKV; \
    const size_t kbase_ = (size_t)(b * TT + (kb) * 32) * DH; \
    const size_t vbase_ = (size_t)b * DH * TT + (size_t)(kb) * 32; \
    _Pragma("unroll") \
    for (int j_ = 0; j_ < 4; j_++) { \
        const int n_ = tid + j_ * 128; \
        const int kr_ = n_ >> 4, kc_ = n_ & 15; \
        CP16(kvb_ + kr_ * AQS + kc_ * 16, g_k + kbase_ + (size_t)kr_ * DH + kc_ * 8); \
        const int vr_ = n_ >> 2, vc_ = n_ & 3; \
        CP16(kvb_ + 8704 + vr_ * AVS + vc_ * 16, g_vt + vbase_ + (size_t)vr_ * TT + vc_ * 8); \
    } \
} while (0)

    const int ntiles = 2 * qt + 2;   // >= 2
    LOADKV(0, 0);
    CP_COMMIT();
    LOADKV(1, 1);
    CP_COMMIT();

    float O[16][4];
#pragma unroll
    for (int i = 0; i < 16; i++)
#pragma unroll
        for (int e = 0; e < 4; e++) O[i][e] = 0.f;
    float m0 = -1e30f, m1 = -1e30f, l0 = 0.f, l1 = 0.f;
    const float sc2 = 0.08838834764831845f * 1.4426950408889634f;
    const int qrow0 = qt * 64 + w * 16 + g;
    const int wrow_max = qt * 64 + w * 16 + 15;

    int buf = 0;
    for (int it = 0; it < ntiles; it++) {
        if (it + 1 < ntiles) CP_WAIT1();
        else                 CP_WAIT0();
        __syncthreads();
        if (it + 2 < ntiles) {
            const int nb = (buf + 2 >= 3) ? buf - 1 : buf + 2;
            LOADKV(nb, it + 2);
            CP_COMMIT();
        }
        const uint32_t kvb = sb0 + QREG + buf * SKV;

        if (it * 32 <= wrow_max) {
            // ---- S = Q K^T (2-pass) ----
            float sS[4][4];
#pragma unroll
            for (int i = 0; i < 4; i++)
#pragma unroll
                for (int e = 0; e < 4; e++) sS[i][e] = 0.f;
#pragma unroll
            for (int kt = 0; kt < 8; kt++) {
                uint32_t kb[4][2];
#pragma unroll
                for (int p = 0; p < 2; p++) {
                    const uint32_t kaddr = kvb + (p * 16 + b_n) * AQS + kt * 32 + b_kb;
                    ldsm_x4(kb[2 * p][0], kb[2 * p][1],
                            kb[2 * p + 1][0], kb[2 * p + 1][1], kaddr);
                }
#pragma unroll
                for (int nt = 0; nt < 4; nt++) mma_f16(sS[nt], aQh[kt], kb[nt]);
#pragma unroll
                for (int nt = 0; nt < 4; nt++) mma_f16(sS[nt], aQl[kt], kb[nt]);
            }

            // ---- online softmax (log2 domain) ----
            const int kcol0 = it * 32 + 2 * t2;
            float ml0 = -1e30f, ml1 = -1e30f;
#pragma unroll
            for (int nt = 0; nt < 4; nt++) {
                const int c = kcol0 + nt * 8;
                float s0 = sS[nt][0] * sc2, s1 = sS[nt][1] * sc2;
                float s2 = sS[nt][2] * sc2, s3 = sS[nt][3] * sc2;
                if (c > qrow0)         s0 = -1e30f;
                if (c + 1 > qrow0)     s1 = -1e30f;
                if (c > qrow0 + 8)     s2 = -1e30f;
                if (c + 1 > qrow0 + 8) s3 = -1e30f;
                sS[nt][0] = s0; sS[nt][1] = s1; sS[nt][2] = s2; sS[nt][3] = s3;
                ml0 = fmaxf(ml0, fmaxf(s0, s1));
                ml1 = fmaxf(ml1, fmaxf(s2, s3));
            }
            ml0 = fmaxf(ml0, __shfl_xor_sync(0xffffffffu, ml0, 1));
            ml0 = fmaxf(ml0, __shfl_xor_sync(0xffffffffu, ml0, 2));
            ml1 = fmaxf(ml1, __shfl_xor_sync(0xffffffffu, ml1, 1));
            ml1 = fmaxf(ml1, __shfl_xor_sync(0xffffffffu, ml1, 2));
            const float mn0 = fmaxf(m0, ml0), mn1 = fmaxf(m1, ml1);
            const float al0 = ex2f(m0 - mn0), al1 = ex2f(m1 - mn1);

            float ps0 = 0.f, ps1 = 0.f;
            uint32_t aPh[2][4], aPl[2][4];
#pragma unroll
            for (int u = 0; u < 2; u++) {
                const float p00 = ex2f(sS[2 * u][0] - mn0);
                const float p01 = ex2f(sS[2 * u][1] - mn0);
                const float p02 = ex2f(sS[2 * u][2] - mn1);
                const float p03 = ex2f(sS[2 * u][3] - mn1);
                const float p10 = ex2f(sS[2 * u + 1][0] - mn0);
                const float p11 = ex2f(sS[2 * u + 1][1] - mn0);
                const float p12 = ex2f(sS[2 * u + 1][2] - mn1);
                const float p13 = ex2f(sS[2 * u + 1][3] - mn1);
                ps0 += p00 + p01 + p10 + p11;
                ps1 += p02 + p03 + p12 + p13;
                aPh[u][0] = spkh_hi(p00, p01); aPl[u][0] = spkh_lo(p00, p01);
                aPh[u][1] = spkh_hi(p02, p03); aPl[u][1] = spkh_lo(p02, p03);
                aPh[u][2] = spkh_hi(p10, p11); aPl[u][2] = spkh_lo(p10, p11);
                aPh[u][3] = spkh_hi(p12, p13); aPl[u][3] = spkh_lo(p12, p13);
            }
            ps0 += __shfl_xor_sync(0xffffffffu, ps0, 1);
            ps0 += __shfl_xor_sync(0xffffffffu, ps0, 2);
            ps1 += __shfl_xor_sync(0xffffffffu, ps1, 1);
            ps1 += __shfl_xor_sync(0xffffffffu, ps1, 2);
            l0 = l0 * al0 + ps0;
            l1 = l1 * al1 + ps1;
            m0 = mn0; m1 = mn1;
#pragma unroll
            for (int i = 0; i < 16; i++) {
                O[i][0] *= al0; O[i][1] *= al0;
                O[i][2] *= al1; O[i][3] *= al1;
            }

            // ---- O += P V (2-pass) ----
#pragma unroll
            for (int u = 0; u < 2; u++) {
#pragma unroll
                for (int pp = 0; pp < 4; pp++) {
                    uint32_t vb[4][2];
#pragma unroll
                    for (int pi = 0; pi < 2; pi++) {
                        const int p = 2 * pp + pi;
                        const uint32_t vaddr =
                            kvb + 8704 + (p * 16 + b_n) * AVS + u * 32 + b_kb;
                        ldsm_x4(vb[2 * pi][0], vb[2 * pi][1],
                                vb[2 * pi + 1][0], vb[2 * pi + 1][1], vaddr);
                    }
#pragma unroll
                    for (int q = 0; q < 4; q++) mma_f16(O[4 * pp + q], aPh[u], vb[q]);
#pragma unroll
                    for (int q = 0; q < 4; q++) mma_f16(O[4 * pp + q], aPl[u], vb[q]);
                }
            }
        }
        buf = (buf == 2) ? 0 : buf + 1;
    }

    const float inv0 = 1.0f / l0, inv1 = 1.0f / l1;
    const size_t obase = (size_t)(b * TT + qrow0) * DM + h * DH;
#pragma unroll
    for (int ntd = 0; ntd < 16; ntd++) {
        const int d = ntd * 8 + 2 * t2;
        const float v0 = O[ntd][0] * inv0, v1 = O[ntd][1] * inv0;
        const float v2 = O[ntd][2] * inv1, v3 = O[ntd][3] * inv1;
        *(uint32_t*)&g_cfh[obase + d] = spkh_hi(v0, v1);
        *(uint32_t*)&g_cfl[obase + d] = spkh_lo(v0, v1);
        *(uint32_t*)&g_cfh[obase + 8 * DM + d] = spkh_hi(v2, v3);
        *(uint32_t*)&g_cfl[obase + 8 * DM + d] = spkh_lo(v2, v3);
    }
}

// ============================================================
extern "C" void kernel_launch(void* const* d_in, const int* in_sizes, int n_in,
                              void* d_out, int out_size)
{
    const float* x  = (const float*)d_in[0];
    const float* Wq = (const float*)d_in[2];
    const float* bq = (const float*)d_in[3];
    const float* Wk = (const float*)d_in[4];
    const float* bk = (const float*)d_in[5];
    const float* Wv = (const float*)d_in[6];
    const float* bv = (const float*)d_in[7];
    const float* Wo = (const float*)d_in[8];
    const float* bo = (const float*)d_in[9];
    float* out = (float*)d_out;

    const int gsmem = 3 * STG;   // 92160
    cudaFuncSetAttribute(tc_gemm, cudaFuncAttributeMaxDynamicSharedMemorySize, gsmem);
    cudaFuncSetAttribute(attn_mma, cudaFuncAttributeMaxDynamicSharedMemorySize, ASMEM);

    prep_kernel<<<12800, 256>>>(x, Wq, Wk, Wv, Wo);

    tc_gemm<<<dim3(18, MROWS / 128), 256, gsmem>>>(bq, bk, bv, nullptr, 0);

    attn_mma<<<dim3(TT / 64, NH, BBAT), 128, ASMEM>>>();

    tc_gemm<<<dim3(16, MROWS / 128), 256, gsmem>>>(bo, nullptr, nullptr, out, 1);
}

// round 15
// speedup vs baseline: 2.3753x; 1.7024x over previous
#include <cuda_runtime.h>
#include <cuda_fp16.h>
#include <cstdint>

#define BBAT 4
#define TT 2048
#define DM 2048
#define NH 16
#define DH 128
#define MROWS (BBAT * TT)

// ---- scratch (single fp16 everywhere) ----
__device__ __half g_xf[(size_t)MROWS * DM];
__device__ __half g_cf[(size_t)MROWS * DM];
__device__ __half g_qf[(size_t)MROWS * DM];
__device__ __half g_k[(size_t)MROWS * DH];
__device__ __half g_vt[(size_t)DH * MROWS];
__device__ __half g_wq[(size_t)DM * DM];
__device__ __half g_wk[(size_t)DH * DM];
__device__ __half g_wv[(size_t)DH * DM];
__device__ __half g_wo[(size_t)DM * DM];

// ---- PTX helpers ----
__device__ __forceinline__ uint32_t smem_u32(const void* p) {
    uint32_t a;
    asm("{ .reg .u64 t; cvta.to.shared.u64 t, %1; cvt.u32.u64 %0, t; }" : "=r"(a) : "l"(p));
    return a;
}
#define CP16(s, g) \
    asm volatile("cp.async.cg.shared.global [%0], [%1], 16;" :: "r"(s), "l"(g))
#define CP_COMMIT() asm volatile("cp.async.commit_group;" ::: "memory")
#define CP_WAIT1() asm volatile("cp.async.wait_group 1;" ::: "memory")
#define CP_WAIT0() asm volatile("cp.async.wait_group 0;" ::: "memory")

__device__ __forceinline__ void ldsm_x4(uint32_t& r0, uint32_t& r1, uint32_t& r2,
                                        uint32_t& r3, uint32_t addr) {
    asm volatile("ldmatrix.sync.aligned.m8n8.x4.shared.b16 {%0,%1,%2,%3}, [%4];"
                 : "=r"(r0), "=r"(r1), "=r"(r2), "=r"(r3) : "r"(addr));
}
__device__ __forceinline__ void mma_f16(float* c, const uint32_t* a, const uint32_t* b) {
    asm volatile("mma.sync.aligned.m16n8k16.row.col.f32.f16.f16.f32 "
                 "{%0,%1,%2,%3}, {%4,%5,%6,%7}, {%8,%9}, {%0,%1,%2,%3};"
                 : "+f"(c[0]), "+f"(c[1]), "+f"(c[2]), "+f"(c[3])
                 : "r"(a[0]), "r"(a[1]), "r"(a[2]), "r"(a[3]), "r"(b[0]), "r"(b[1]));
}
__device__ __forceinline__ float ex2f(float x) {
    float y;
    asm("ex2.approx.f32 %0, %1;" : "=f"(y) : "f"(x));
    return y;
}
__device__ __forceinline__ uint32_t pk2h(__half a, __half b) {
    return (uint32_t)__half_as_ushort(a) | ((uint32_t)__half_as_ushort(b) << 16);
}
__device__ __forceinline__ uint32_t spkh(float a, float b) {
    return pk2h(__float2half_rn(a), __float2half_rn(b));
}

// ============================================================
// Fused prep:
//  [0,2048)      x -> single fp16
//  [2048,6144)   Wq -> single fp16 transposed
//  [6144,6400)   Wk
//  [6400,6656)   Wv
//  [6656,10752)  Wo
// ============================================================
__device__ __forceinline__ void do_tsingle_h(const float* __restrict__ W,
                                             __half* dst, int Kd, int Nd, int bx2,
                                             float (*t)[33]) {
    const int xw = Nd / 32;
    const int nb = (bx2 % xw) * 32, kb = (bx2 / xw) * 32;
    const int tx = threadIdx.x & 31, ty = threadIdx.x >> 5;
#pragma unroll
    for (int i = 0; i < 4; i++)
        t[ty + 8 * i][tx] = W[(size_t)(kb + ty + 8 * i) * Nd + nb + tx];
    __syncthreads();
#pragma unroll
    for (int i = 0; i < 4; i++) {
        const int nrow = ty + 8 * i;
        dst[(size_t)(nb + nrow) * Kd + kb + tx] = __float2half_rn(t[tx][nrow]);
    }
}

__global__ __launch_bounds__(256) void prep_kernel(
    const float* __restrict__ x, const float* __restrict__ Wq,
    const float* __restrict__ Wk, const float* __restrict__ Wv,
    const float* __restrict__ Wo)
{
    __shared__ float t[32][33];
    const int bx = blockIdx.x;
    if (bx < 2048) {
        const int n4 = MROWS * DM / 4;
        for (int i = bx * 256 + threadIdx.x; i < n4; i += 2048 * 256) {
            float4 v = ((const float4*)x)[i];
            uint2 F;
            F.x = spkh(v.x, v.y);
            F.y = spkh(v.z, v.w);
            ((uint2*)g_xf)[i] = F;
        }
    } else if (bx < 6144) {
        do_tsingle_h(Wq, g_wq, DM, DM, bx - 2048, t);
    } else if (bx < 6400) {
        do_tsingle_h(Wk, g_wk, DM, DH, bx - 6144, t);
    } else if (bx < 6656) {
        do_tsingle_h(Wv, g_wv, DM, DH, bx - 6400, t);
    } else {
        do_tsingle_h(Wo, g_wo, DM, DM, bx - 6656, t);
    }
}

// ============================================================
// fp16 single-pass GEMM, 3-stage cp.async, one barrier/iter.
// stage: A@0, B@10240 (rows 128x80B). STG=20480, 3 stages.
// mode 0 = QKV (bx<16 Q, 16 K, 17 V-transposed); mode 1 = O proj.
// ============================================================
#define STG 20480

__global__ __launch_bounds__(256, 2) void tc_gemm(
    const float* __restrict__ b0, const float* __restrict__ b1,
    const float* __restrict__ b2, float* __restrict__ Cext, int mode)
{
    extern __shared__ char sm[];
    const uint32_t sbase = smem_u32(sm);
    const int tid = threadIdx.x;
    const int lane = tid & 31, warp = tid >> 5;
    const int wm = warp & 3, wn = warp >> 2;
    const int bx = blockIdx.x;
    const int rowBase = blockIdx.y * 128;

    const __half* A = mode ? g_cf : g_xf;
    const __half* B;
    int wRow0;
    if (mode) { B = g_wo; wRow0 = bx * 128; }
    else if (bx < 16)  { B = g_wq; wRow0 = bx * 128; }
    else if (bx == 16) { B = g_wk; wRow0 = 0; }
    else               { B = g_wv; wRow0 = 0; }

    float acc[2][8][4];
#pragma unroll
    for (int mt = 0; mt < 2; mt++)
#pragma unroll
        for (int nt = 0; nt < 8; nt++)
#pragma unroll
            for (int e = 0; e < 4; e++) acc[mt][nt][e] = 0.f;

    const int lr = tid >> 2, lc = tid & 3;
    const int a_r = lane & 15;
    const uint32_t a_kb = (lane & 16) ? 16 : 0;
    const int b_n = (lane & 7) + ((lane & 16) ? 8 : 0);
    const uint32_t b_kb = (lane & 8) ? 16 : 0;
    const int g = lane >> 2, t2 = lane & 3;

#define LOAD_STAGE(buf, k0) do { \
    const uint32_t sb_ = sbase + (buf) * STG; \
    _Pragma("unroll") \
    for (int h_ = 0; h_ < 2; h_++) { \
        const int r_ = lr + h_ * 64; \
        const uint32_t so_ = r_ * 80 + lc * 16; \
        const size_t ga_ = (size_t)(rowBase + r_) * DM + (k0) + lc * 8; \
        const size_t gb_ = (size_t)(wRow0 + r_) * DM + (k0) + lc * 8; \
        CP16(sb_ + so_, A + ga_); \
        CP16(sb_ + 10240 + so_, B + gb_); \
    } \
} while (0)

    LOAD_STAGE(0, 0);
    CP_COMMIT();
    LOAD_STAGE(1, 32);
    CP_COMMIT();

    const int ITERS = DM / 32;   // 64
    int buf = 0;
    for (int s = 0; s < ITERS; s++) {
        if (s + 1 < ITERS) CP_WAIT1();
        else               CP_WAIT0();
        __syncthreads();
        if (s + 2 < ITERS) {
            const int nb = (buf + 2 >= 3) ? buf - 1 : buf + 2;
            LOAD_STAGE(nb, (s + 2) * 32);
            CP_COMMIT();
        }

        const uint32_t sb = sbase + buf * STG;
#pragma unroll
        for (int ks = 0; ks < 2; ks++) {
            const uint32_t kso = ks * 32;
            uint32_t ah[2][4], bb[8][2];
#pragma unroll
            for (int mt = 0; mt < 2; mt++) {
                const uint32_t addr = sb + (wm * 32 + mt * 16 + a_r) * 80 + kso + a_kb;
                ldsm_x4(ah[mt][0], ah[mt][1], ah[mt][2], ah[mt][3], addr);
            }
#pragma unroll
            for (int p = 0; p < 4; p++) {
                const uint32_t addr = sb + 10240 + (wn * 64 + p * 16 + b_n) * 80 + kso + b_kb;
                ldsm_x4(bb[p * 2][0], bb[p * 2][1], bb[p * 2 + 1][0], bb[p * 2 + 1][1], addr);
            }
#pragma unroll
            for (int mt = 0; mt < 2; mt++)
#pragma unroll
                for (int nt = 0; nt < 8; nt++)
                    mma_f16(acc[mt][nt], ah[mt], bb[nt]);
        }
        buf = (buf == 2) ? 0 : buf + 1;
    }

    if (mode) {
#pragma unroll
        for (int mt = 0; mt < 2; mt++) {
            const int r0 = rowBase + wm * 32 + mt * 16 + g;
#pragma unroll
            for (int nt = 0; nt < 8; nt++) {
                const int col = bx * 128 + wn * 64 + nt * 8 + t2 * 2;
                const float bxv = b0[col], byv = b0[col + 1];
                float2 o0, o1;
                o0.x = acc[mt][nt][0] + bxv; o0.y = acc[mt][nt][1] + byv;
                o1.x = acc[mt][nt][2] + bxv; o1.y = acc[mt][nt][3] + byv;
                *(float2*)(Cext + (size_t)r0 * DM + col) = o0;
                *(float2*)(Cext + (size_t)(r0 + 8) * DM + col) = o1;
            }
        }
    } else if (bx < 16) {
#pragma unroll
        for (int mt = 0; mt < 2; mt++) {
            const int r0 = rowBase + wm * 32 + mt * 16 + g;
#pragma unroll
            for (int nt = 0; nt < 8; nt++) {
                const int col = bx * 128 + wn * 64 + nt * 8 + t2 * 2;
                const float bxv = b0[col], byv = b0[col + 1];
                const float v0 = acc[mt][nt][0] + bxv, v1 = acc[mt][nt][1] + byv;
                const float v2 = acc[mt][nt][2] + bxv, v3 = acc[mt][nt][3] + byv;
                *(uint32_t*)&g_qf[(size_t)r0 * DM + col] = spkh(v0, v1);
                *(uint32_t*)&g_qf[(size_t)(r0 + 8) * DM + col] = spkh(v2, v3);
            }
        }
    } else if (bx == 16) {
#pragma unroll
        for (int mt = 0; mt < 2; mt++) {
            const int r0 = rowBase + wm * 32 + mt * 16 + g;
#pragma unroll
            for (int nt = 0; nt < 8; nt++) {
                const int col = wn * 64 + nt * 8 + t2 * 2;
                const float bxv = b1[col], byv = b1[col + 1];
                const float v0 = acc[mt][nt][0] + bxv, v1 = acc[mt][nt][1] + byv;
                const float v2 = acc[mt][nt][2] + bxv, v3 = acc[mt][nt][3] + byv;
                *(uint32_t*)&g_k[(size_t)r0 * DH + col] = spkh(v0, v1);
                *(uint32_t*)&g_k[(size_t)(r0 + 8) * DH + col] = spkh(v2, v3);
            }
        }
    } else {
#pragma unroll
        for (int mt = 0; mt < 2; mt++) {
            const int r0 = rowBase + wm * 32 + mt * 16 + g;
            const int bidx = r0 >> 11;
            const int trow = r0 & (TT - 1);
#pragma unroll
            for (int nt = 0; nt < 8; nt++) {
                const int col = wn * 64 + nt * 8 + t2 * 2;
                const float bxv = b2[col], byv = b2[col + 1];
                const float v0 = acc[mt][nt][0] + bxv, v1 = acc[mt][nt][1] + byv;
                const float v2 = acc[mt][nt][2] + bxv, v3 = acc[mt][nt][3] + byv;
                const size_t base0 = ((size_t)bidx * DH + col) * TT + trow;
                g_vt[base0]          = __float2half_rn(v0);
                g_vt[base0 + TT]     = __float2half_rn(v1);
                g_vt[base0 + 8]      = __float2half_rn(v2);
                g_vt[base0 + TT + 8] = __float2half_rn(v3);
            }
        }
    }
}

// ============================================================
// Flash attention, all single fp16: Q·K 1-pass, P·V 1-pass.
// 128-thr CTAs, BN=32, 3-stage KV, 2 CTAs/SM.
// smem: Q 0 (64x272=17408); stage s @ 17408+s*18944:
//   K +0 (32x272=8704), Vt +8704 (128x80=10240)
// ============================================================
#define AQS 272
#define AVS 80
#define QREG 17408
#define SKV 18944
#define ASMEM (QREG + 3 * SKV)   // 74240

__global__ __launch_bounds__(128, 2) void attn_mma()
{
    extern __shared__ char sm[];
    const uint32_t sb0 = smem_u32(sm);
    const int qt = gridDim.x - 1 - blockIdx.x;
    const int h = blockIdx.y, b = blockIdx.z;
    const int tid = threadIdx.x, lane = tid & 31, w = tid >> 5;
    const int g = lane >> 2, t2 = lane & 3;
    const int a_r = lane & 15;
    const uint32_t a_kb = (lane & 16) ? 16 : 0;
    const int b_n = (lane & 7) + ((lane & 16) ? 8 : 0);
    const uint32_t b_kb = (lane & 8) ? 16 : 0;

    {
        const size_t qbase = (size_t)(b * TT + qt * 64) * DM + h * DH;
#pragma unroll
        for (int j = 0; j < 8; j++) {
            const int n = tid + j * 128;
            const int row = n >> 4, ch = n & 15;
            CP16(sb0 + row * AQS + ch * 16, g_qf + qbase + (size_t)row * DM + ch * 8);
        }
    }
    CP_COMMIT();
    CP_WAIT0();
    __syncthreads();

    uint32_t aQ[8][4];
#pragma unroll
    for (int kt = 0; kt < 8; kt++) {
        const uint32_t qaddr = sb0 + (w * 16 + a_r) * AQS + kt * 32 + a_kb;
        ldsm_x4(aQ[kt][0], aQ[kt][1], aQ[kt][2], aQ[kt][3], qaddr);
    }

#define LOADKV(buf, kb) do { \
    const uint32_t kvb_ = sb0 + QREG + (buf) * SKV; \
    const size_t kbase_ = (size_t)(b * TT + (kb) * 32) * DH; \
    const size_t vbase_ = (size_t)b * DH * TT + (size_t)(kb) * 32; \
    _Pragma("unroll") \
    for (int j_ = 0; j_ < 4; j_++) { \
        const int n_ = tid + j_ * 128; \
        const int kr_ = n_ >> 4, kc_ = n_ & 15; \
        CP16(kvb_ + kr_ * AQS + kc_ * 16, g_k + kbase_ + (size_t)kr_ * DH + kc_ * 8); \
        const int vr_ = n_ >> 2, vc_ = n_ & 3; \
        CP16(kvb_ + 8704 + vr_ * AVS + vc_ * 16, g_vt + vbase_ + (size_t)vr_ * TT + vc_ * 8); \
    } \
} while (0)

    const int ntiles = 2 * qt + 2;
    LOADKV(0, 0);
    CP_COMMIT();
    LOADKV(1, 1);
    CP_COMMIT();

    float O[16][4];
#pragma unroll
    for (int i = 0; i < 16; i++)
#pragma unroll
        for (int e = 0; e < 4; e++) O[i][e] = 0.f;
    float m0 = -1e30f, m1 = -1e30f, l0 = 0.f, l1 = 0.f;
    const float sc2 = 0.08838834764831845f * 1.4426950408889634f;
    const int qrow0 = qt * 64 + w * 16 + g;
    const int wrow_max = qt * 64 + w * 16 + 15;

    int buf = 0;
    for (int it = 0; it < ntiles; it++) {
        if (it + 1 < ntiles) CP_WAIT1();
        else                 CP_WAIT0();
        __syncthreads();
        if (it + 2 < ntiles) {
            const int nb = (buf + 2 >= 3) ? buf - 1 : buf + 2;
            LOADKV(nb, it + 2);
            CP_COMMIT();
        }
        const uint32_t kvb = sb0 + QREG + buf * SKV;

        if (it * 32 <= wrow_max) {
            // ---- S = Q K^T (single pass) ----
            float sS[4][4];
#pragma unroll
            for (int i = 0; i < 4; i++)
#pragma unroll
                for (int e = 0; e < 4; e++) sS[i][e] = 0.f;
#pragma unroll
            for (int kt = 0; kt < 8; kt++) {
                uint32_t kb[4][2];
#pragma unroll
                for (int p = 0; p < 2; p++) {
                    const uint32_t kaddr = kvb + (p * 16 + b_n) * AQS + kt * 32 + b_kb;
                    ldsm_x4(kb[2 * p][0], kb[2 * p][1],
                            kb[2 * p + 1][0], kb[2 * p + 1][1], kaddr);
                }
#pragma unroll
                for (int nt = 0; nt < 4; nt++) mma_f16(sS[nt], aQ[kt], kb[nt]);
            }

            // ---- online softmax (log2 domain) ----
            const int kcol0 = it * 32 + 2 * t2;
            float ml0 = -1e30f, ml1 = -1e30f;
#pragma unroll
            for (int nt = 0; nt < 4; nt++) {
                const int c = kcol0 + nt * 8;
                float s0 = sS[nt][0] * sc2, s1 = sS[nt][1] * sc2;
                float s2 = sS[nt][2] * sc2, s3 = sS[nt][3] * sc2;
                if (c > qrow0)         s0 = -1e30f;
                if (c + 1 > qrow0)     s1 = -1e30f;
                if (c > qrow0 + 8)     s2 = -1e30f;
                if (c + 1 > qrow0 + 8) s3 = -1e30f;
                sS[nt][0] = s0; sS[nt][1] = s1; sS[nt][2] = s2; sS[nt][3] = s3;
                ml0 = fmaxf(ml0, fmaxf(s0, s1));
                ml1 = fmaxf(ml1, fmaxf(s2, s3));
            }
            ml0 = fmaxf(ml0, __shfl_xor_sync(0xffffffffu, ml0, 1));
            ml0 = fmaxf(ml0, __shfl_xor_sync(0xffffffffu, ml0, 2));
            ml1 = fmaxf(ml1, __shfl_xor_sync(0xffffffffu, ml1, 1));
            ml1 = fmaxf(ml1, __shfl_xor_sync(0xffffffffu, ml1, 2));
            const float mn0 = fmaxf(m0, ml0), mn1 = fmaxf(m1, ml1);
            const float al0 = ex2f(m0 - mn0), al1 = ex2f(m1 - mn1);

            float ps0 = 0.f, ps1 = 0.f;
            uint32_t aP[2][4];
#pragma unroll
            for (int u = 0; u < 2; u++) {
                const float p00 = ex2f(sS[2 * u][0] - mn0);
                const float p01 = ex2f(sS[2 * u][1] - mn0);
                const float p02 = ex2f(sS[2 * u][2] - mn1);
                const float p03 = ex2f(sS[2 * u][3] - mn1);
                const float p10 = ex2f(sS[2 * u + 1][0] - mn0);
                const float p11 = ex2f(sS[2 * u + 1][1] - mn0);
                const float p12 = ex2f(sS[2 * u + 1][2] - mn1);
                const float p13 = ex2f(sS[2 * u + 1][3] - mn1);
                ps0 += p00 + p01 + p10 + p11;
                ps1 += p02 + p03 + p12 + p13;
                aP[u][0] = spkh(p00, p01);
                aP[u][1] = spkh(p02, p03);
                aP[u][2] = spkh(p10, p11);
                aP[u][3] = spkh(p12, p13);
            }
            ps0 += __shfl_xor_sync(0xffffffffu, ps0, 1);
            ps0 += __shfl_xor_sync(0xffffffffu, ps0, 2);
            ps1 += __shfl_xor_sync(0xffffffffu, ps1, 1);
            ps1 += __shfl_xor_sync(0xffffffffu, ps1, 2);
            l0 = l0 * al0 + ps0;
            l1 = l1 * al1 + ps1;
            m0 = mn0; m1 = mn1;
#pragma unroll
            for (int i = 0; i < 16; i++) {
                O[i][0] *= al0; O[i][1] *= al0;
                O[i][2] *= al1; O[i][3] *= al1;
            }

            // ---- O += P V (single pass) ----
#pragma unroll
            for (int u = 0; u < 2; u++) {
#pragma unroll
                for (int pp = 0; pp < 4; pp++) {
                    uint32_t vb[4][2];
#pragma unroll
                    for (int pi = 0; pi < 2; pi++) {
                        const int p = 2 * pp + pi;
                        const uint32_t vaddr =
                            kvb + 8704 + (p * 16 + b_n) * AVS + u * 32 + b_kb;
                        ldsm_x4(vb[2 * pi][0], vb[2 * pi][1],
                                vb[2 * pi + 1][0], vb[2 * pi + 1][1], vaddr);
                    }
#pragma unroll
                    for (int q = 0; q < 4; q++) mma_f16(O[4 * pp + q], aP[u], vb[q]);
                }
            }
        }
        buf = (buf == 2) ? 0 : buf + 1;
    }

    const float inv0 = 1.0f / l0, inv1 = 1.0f / l1;
    const size_t obase = (size_t)(b * TT + qrow0) * DM + h * DH;
#pragma unroll
    for (int ntd = 0; ntd < 16; ntd++) {
        const int d = ntd * 8 + 2 * t2;
        const float v0 = O[ntd][0] * inv0, v1 = O[ntd][1] * inv0;
        const float v2 = O[ntd][2] * inv1, v3 = O[ntd][3] * inv1;
        *(uint32_t*)&g_cf[obase + d] = spkh(v0, v1);
        *(uint32_t*)&g_cf[obase + 8 * DM + d] = spkh(v2, v3);
    }
}

// ============================================================
extern "C" void kernel_launch(void* const* d_in, const int* in_sizes, int n_in,
                              void* d_out, int out_size)
{
    const float* x  = (const float*)d_in[0];
    const float* Wq = (const float*)d_in[2];
    const float* bq = (const float*)d_in[3];
    const float* Wk = (const float*)d_in[4];
    const float* bk = (const float*)d_in[5];
    const float* Wv = (const float*)d_in[6];
    const float* bv = (const float*)d_in[7];
    const float* Wo = (const float*)d_in[8];
    const float* bo = (const float*)d_in[9];
    float* out = (float*)d_out;

    const int gsmem = 3 * STG;   // 61440
    cudaFuncSetAttribute(tc_gemm, cudaFuncAttributeMaxDynamicSharedMemorySize, gsmem);
    cudaFuncSetAttribute(attn_mma, cudaFuncAttributeMaxDynamicSharedMemorySize, ASMEM);

    prep_kernel<<<10752, 256>>>(x, Wq, Wk, Wv, Wo);

    tc_gemm<<<dim3(18, MROWS / 128), 256, gsmem>>>(bq, bk, bv, nullptr, 0);

    attn_mma<<<dim3(TT / 64, NH, BBAT), 128, ASMEM>>>();

    tc_gemm<<<dim3(16, MROWS / 128), 256, gsmem>>>(bo, nullptr, nullptr, out, 1);
}

// round 16
// speedup vs baseline: 2.4189x; 1.0184x over previous
#include <cuda_runtime.h>
#include <cuda_fp16.h>
#include <cstdint>

#define BBAT 4
#define TT 2048
#define DM 2048
#define NH 16
#define DH 128
#define MROWS (BBAT * TT)

// ---- scratch (single fp16 everywhere) ----
__device__ __half g_xf[(size_t)MROWS * DM];
__device__ __half g_cf[(size_t)MROWS * DM];
__device__ __half g_qf[(size_t)MROWS * DM];
__device__ __half g_k[(size_t)MROWS * DH];
__device__ __half g_vt[(size_t)DH * MROWS];
__device__ __half g_wq[(size_t)DM * DM];
__device__ __half g_wk[(size_t)DH * DM];
__device__ __half g_wv[(size_t)DH * DM];
__device__ __half g_wo[(size_t)DM * DM];

// ---- PTX helpers ----
__device__ __forceinline__ uint32_t smem_u32(const void* p) {
    uint32_t a;
    asm("{ .reg .u64 t; cvta.to.shared.u64 t, %1; cvt.u32.u64 %0, t; }" : "=r"(a) : "l"(p));
    return a;
}
#define CP16(s, g) \
    asm volatile("cp.async.cg.shared.global [%0], [%1], 16;" :: "r"(s), "l"(g))
#define CP_COMMIT() asm volatile("cp.async.commit_group;" ::: "memory")
#define CP_WAIT1() asm volatile("cp.async.wait_group 1;" ::: "memory")
#define CP_WAIT0() asm volatile("cp.async.wait_group 0;" ::: "memory")

__device__ __forceinline__ void ldsm_x4(uint32_t& r0, uint32_t& r1, uint32_t& r2,
                                        uint32_t& r3, uint32_t addr) {
    asm volatile("ldmatrix.sync.aligned.m8n8.x4.shared.b16 {%0,%1,%2,%3}, [%4];"
                 : "=r"(r0), "=r"(r1), "=r"(r2), "=r"(r3) : "r"(addr));
}
__device__ __forceinline__ void mma_f16(float* c, const uint32_t* a, const uint32_t* b) {
    asm volatile("mma.sync.aligned.m16n8k16.row.col.f32.f16.f16.f32 "
                 "{%0,%1,%2,%3}, {%4,%5,%6,%7}, {%8,%9}, {%0,%1,%2,%3};"
                 : "+f"(c[0]), "+f"(c[1]), "+f"(c[2]), "+f"(c[3])
                 : "r"(a[0]), "r"(a[1]), "r"(a[2]), "r"(a[3]), "r"(b[0]), "r"(b[1]));
}
__device__ __forceinline__ float ex2f(float x) {
    float y;
    asm("ex2.approx.f32 %0, %1;" : "=f"(y) : "f"(x));
    return y;
}
__device__ __forceinline__ uint32_t pk2h(__half a, __half b) {
    return (uint32_t)__half_as_ushort(a) | ((uint32_t)__half_as_ushort(b) << 16);
}
__device__ __forceinline__ uint32_t spkh(float a, float b) {
    return pk2h(__float2half_rn(a), __float2half_rn(b));
}

// ============================================================
// Fused prep (unchanged)
// ============================================================
__device__ __forceinline__ void do_tsingle_h(const float* __restrict__ W,
                                             __half* dst, int Kd, int Nd, int bx2,
                                             float (*t)[33]) {
    const int xw = Nd / 32;
    const int nb = (bx2 % xw) * 32, kb = (bx2 / xw) * 32;
    const int tx = threadIdx.x & 31, ty = threadIdx.x >> 5;
#pragma unroll
    for (int i = 0; i < 4; i++)
        t[ty + 8 * i][tx] = W[(size_t)(kb + ty + 8 * i) * Nd + nb + tx];
    __syncthreads();
#pragma unroll
    for (int i = 0; i < 4; i++) {
        const int nrow = ty + 8 * i;
        dst[(size_t)(nb + nrow) * Kd + kb + tx] = __float2half_rn(t[tx][nrow]);
    }
}

__global__ __launch_bounds__(256) void prep_kernel(
    const float* __restrict__ x, const float* __restrict__ Wq,
    const float* __restrict__ Wk, const float* __restrict__ Wv,
    const float* __restrict__ Wo)
{
    __shared__ float t[32][33];
    const int bx = blockIdx.x;
    if (bx < 2048) {
        const int n4 = MROWS * DM / 4;
        for (int i = bx * 256 + threadIdx.x; i < n4; i += 2048 * 256) {
            float4 v = ((const float4*)x)[i];
            uint2 F;
            F.x = spkh(v.x, v.y);
            F.y = spkh(v.z, v.w);
            ((uint2*)g_xf)[i] = F;
        }
    } else if (bx < 6144) {
        do_tsingle_h(Wq, g_wq, DM, DM, bx - 2048, t);
    } else if (bx < 6400) {
        do_tsingle_h(Wk, g_wk, DM, DH, bx - 6144, t);
    } else if (bx < 6656) {
        do_tsingle_h(Wv, g_wv, DM, DH, bx - 6400, t);
    } else {
        do_tsingle_h(Wo, g_wo, DM, DM, bx - 6656, t);
    }
}

// ============================================================
// fp16 single-pass GEMM, 128 threads (4 warps, 2x2 grid, 64x64
// per warp), 3-stage cp.async, one barrier/iter.
// stage: A@0, B@10240 (rows 128x80B). STG=20480, 3 stages.
// mode 0 = QKV (bx<16 Q, 16 K, 17 V-transposed); mode 1 = O proj.
// ============================================================
#define STG 20480

__global__ __launch_bounds__(128, 2) void tc_gemm(
    const float* __restrict__ b0, const float* __restrict__ b1,
    const float* __restrict__ b2, float* __restrict__ Cext, int mode)
{
    extern __shared__ char sm[];
    const uint32_t sbase = smem_u32(sm);
    const int tid = threadIdx.x;
    const int lane = tid & 31, warp = tid >> 5;
    const int wm = warp & 1, wn = warp >> 1;     // 2x2 warp grid, 64x64 each
    const int bx = blockIdx.x;
    const int rowBase = blockIdx.y * 128;

    const __half* A = mode ? g_cf : g_xf;
    const __half* B;
    int wRow0;
    if (mode) { B = g_wo; wRow0 = bx * 128; }
    else if (bx < 16)  { B = g_wq; wRow0 = bx * 128; }
    else if (bx == 16) { B = g_wk; wRow0 = 0; }
    else               { B = g_wv; wRow0 = 0; }

    float acc[4][8][4];
#pragma unroll
    for (int mt = 0; mt < 4; mt++)
#pragma unroll
        for (int nt = 0; nt < 8; nt++)
#pragma unroll
            for (int e = 0; e < 4; e++) acc[mt][nt][e] = 0.f;

    const int lr = tid >> 2, lc = tid & 3;       // 32 rows x 4 chunks per pass
    const int a_r = lane & 15;
    const uint32_t a_kb = (lane & 16) ? 16 : 0;
    const int b_n = (lane & 7) + ((lane & 16) ? 8 : 0);
    const uint32_t b_kb = (lane & 8) ? 16 : 0;
    const int g = lane >> 2, t2 = lane & 3;

#define LOAD_STAGE(buf, k0) do { \
    const uint32_t sb_ = sbase + (buf) * STG; \
    _Pragma("unroll") \
    for (int h_ = 0; h_ < 4; h_++) { \
        const int r_ = lr + h_ * 32; \
        const uint32_t so_ = r_ * 80 + lc * 16; \
        const size_t ga_ = (size_t)(rowBase + r_) * DM + (k0) + lc * 8; \
        const size_t gb_ = (size_t)(wRow0 + r_) * DM + (k0) + lc * 8; \
        CP16(sb_ + so_, A + ga_); \
        CP16(sb_ + 10240 + so_, B + gb_); \
    } \
} while (0)

    LOAD_STAGE(0, 0);
    CP_COMMIT();
    LOAD_STAGE(1, 32);
    CP_COMMIT();

    const int ITERS = DM / 32;   // 64
    int buf = 0;
    for (int s = 0; s < ITERS; s++) {
        if (s + 1 < ITERS) CP_WAIT1();
        else               CP_WAIT0();
        __syncthreads();
        if (s + 2 < ITERS) {
            const int nb = (buf + 2 >= 3) ? buf - 1 : buf + 2;
            LOAD_STAGE(nb, (s + 2) * 32);
            CP_COMMIT();
        }

        const uint32_t sb = sbase + buf * STG;
#pragma unroll
        for (int ks = 0; ks < 2; ks++) {
            const uint32_t kso = ks * 32;
            uint32_t ah[4][4], bb[8][2];
#pragma unroll
            for (int mt = 0; mt < 4; mt++) {
                const uint32_t addr = sb + (wm * 64 + mt * 16 + a_r) * 80 + kso + a_kb;
                ldsm_x4(ah[mt][0], ah[mt][1], ah[mt][2], ah[mt][3], addr);
            }
#pragma unroll
            for (int p = 0; p < 4; p++) {
                const uint32_t addr = sb + 10240 + (wn * 64 + p * 16 + b_n) * 80 + kso + b_kb;
                ldsm_x4(bb[p * 2][0], bb[p * 2][1], bb[p * 2 + 1][0], bb[p * 2 + 1][1], addr);
            }
#pragma unroll
            for (int mt = 0; mt < 4; mt++)
#pragma unroll
                for (int nt = 0; nt < 8; nt++)
                    mma_f16(acc[mt][nt], ah[mt], bb[nt]);
        }
        buf = (buf == 2) ? 0 : buf + 1;
    }

    if (mode) {
#pragma unroll
        for (int mt = 0; mt < 4; mt++) {
            const int r0 = rowBase + wm * 64 + mt * 16 + g;
#pragma unroll
            for (int nt = 0; nt < 8; nt++) {
                const int col = bx * 128 + wn * 64 + nt * 8 + t2 * 2;
                const float bxv = b0[col], byv = b0[col + 1];
                float2 o0, o1;
                o0.x = acc[mt][nt][0] + bxv; o0.y = acc[mt][nt][1] + byv;
                o1.x = acc[mt][nt][2] + bxv; o1.y = acc[mt][nt][3] + byv;
                *(float2*)(Cext + (size_t)r0 * DM + col) = o0;
                *(float2*)(Cext + (size_t)(r0 + 8) * DM + col) = o1;
            }
        }
    } else if (bx < 16) {
#pragma unroll
        for (int mt = 0; mt < 4; mt++) {
            const int r0 = rowBase + wm * 64 + mt * 16 + g;
#pragma unroll
            for (int nt = 0; nt < 8; nt++) {
                const int col = bx * 128 + wn * 64 + nt * 8 + t2 * 2;
                const float bxv = b0[col], byv = b0[col + 1];
                const float v0 = acc[mt][nt][0] + bxv, v1 = acc[mt][nt][1] + byv;
                const float v2 = acc[mt][nt][2] + bxv, v3 = acc[mt][nt][3] + byv;
                *(uint32_t*)&g_qf[(size_t)r0 * DM + col] = spkh(v0, v1);
                *(uint32_t*)&g_qf[(size_t)(r0 + 8) * DM + col] = spkh(v2, v3);
            }
        }
    } else if (bx == 16) {
#pragma unroll
        for (int mt = 0; mt < 4; mt++) {
            const int r0 = rowBase + wm * 64 + mt * 16 + g;
#pragma unroll
            for (int nt = 0; nt < 8; nt++) {
                const int col = wn * 64 + nt * 8 + t2 * 2;
                const float bxv = b1[col], byv = b1[col + 1];
                const float v0 = acc[mt][nt][0] + bxv, v1 = acc[mt][nt][1] + byv;
                const float v2 = acc[mt][nt][2] + bxv, v3 = acc[mt][nt][3] + byv;
                *(uint32_t*)&g_k[(size_t)r0 * DH + col] = spkh(v0, v1);
                *(uint32_t*)&g_k[(size_t)(r0 + 8) * DH + col] = spkh(v2, v3);
            }
        }
    } else {
#pragma unroll
        for (int mt = 0; mt < 4; mt++) {
            const int r0 = rowBase + wm * 64 + mt * 16 + g;
            const int bidx = r0 >> 11;
            const int trow = r0 & (TT - 1);
#pragma unroll
            for (int nt = 0; nt < 8; nt++) {
                const int col = wn * 64 + nt * 8 + t2 * 2;
                const float bxv = b2[col], byv = b2[col + 1];
                const float v0 = acc[mt][nt][0] + bxv, v1 = acc[mt][nt][1] + byv;
                const float v2 = acc[mt][nt][2] + bxv, v3 = acc[mt][nt][3] + byv;
                const size_t base0 = ((size_t)bidx * DH + col) * TT + trow;
                g_vt[base0]          = __float2half_rn(v0);
                g_vt[base0 + TT]     = __float2half_rn(v1);
                g_vt[base0 + 8]      = __float2half_rn(v2);
                g_vt[base0 + TT + 8] = __float2half_rn(v3);
            }
        }
    }
}

// ============================================================
// Flash attention, all single fp16 (validated R15, unchanged).
// ============================================================
#define AQS 272
#define AVS 80
#define QREG 17408
#define SKV 18944
#define ASMEM (QREG + 3 * SKV)   // 74240

__global__ __launch_bounds__(128, 2) void attn_mma()
{
    extern __shared__ char sm[];
    const uint32_t sb0 = smem_u32(sm);
    const int qt = gridDim.x - 1 - blockIdx.x;
    const int h = blockIdx.y, b = blockIdx.z;
    const int tid = threadIdx.x, lane = tid & 31, w = tid >> 5;
    const int g = lane >> 2, t2 = lane & 3;
    const int a_r = lane & 15;
    const uint32_t a_kb = (lane & 16) ? 16 : 0;
    const int b_n = (lane & 7) + ((lane & 16) ? 8 : 0);
    const uint32_t b_kb = (lane & 8) ? 16 : 0;

    {
        const size_t qbase = (size_t)(b * TT + qt * 64) * DM + h * DH;
#pragma unroll
        for (int j = 0; j < 8; j++) {
            const int n = tid + j * 128;
            const int row = n >> 4, ch = n & 15;
            CP16(sb0 + row * AQS + ch * 16, g_qf + qbase + (size_t)row * DM + ch * 8);
        }
    }
    CP_COMMIT();
    CP_WAIT0();
    __syncthreads();

    uint32_t aQ[8][4];
#pragma unroll
    for (int kt = 0; kt < 8; kt++) {
        const uint32_t qaddr = sb0 + (w * 16 + a_r) * AQS + kt * 32 + a_kb;
        ldsm_x4(aQ[kt][0], aQ[kt][1], aQ[kt][2], aQ[kt][3], qaddr);
    }

#define LOADKV(buf, kb) do { \
    const uint32_t kvb_ = sb0 + QREG + (buf) * SKV; \
    const size_t kbase_ = (size_t)(b * TT + (kb) * 32) * DH; \
    const size_t vbase_ = (size_t)b * DH * TT + (size_t)(kb) * 32; \
    _Pragma("unroll") \
    for (int j_ = 0; j_ < 4; j_++) { \
        const int n_ = tid + j_ * 128; \
        const int kr_ = n_ >> 4, kc_ = n_ & 15; \
        CP16(kvb_ + kr_ * AQS + kc_ * 16, g_k + kbase_ + (size_t)kr_ * DH + kc_ * 8); \
        const int vr_ = n_ >> 2, vc_ = n_ & 3; \
        CP16(kvb_ + 8704 + vr_ * AVS + vc_ * 16, g_vt + vbase_ + (size_t)vr_ * TT + vc_ * 8); \
    } \
} while (0)

    const int ntiles = 2 * qt + 2;
    LOADKV(0, 0);
    CP_COMMIT();
    LOADKV(1, 1);
    CP_COMMIT();

    float O[16][4];
#pragma unroll
    for (int i = 0; i < 16; i++)
#pragma unroll
        for (int e = 0; e < 4; e++) O[i][e] = 0.f;
    float m0 = -1e30f, m1 = -1e30f, l0 = 0.f, l1 = 0.f;
    const float sc2 = 0.08838834764831845f * 1.4426950408889634f;
    const int qrow0 = qt * 64 + w * 16 + g;
    const int wrow_max = qt * 64 + w * 16 + 15;

    int buf = 0;
    for (int it = 0; it < ntiles; it++) {
        if (it + 1 < ntiles) CP_WAIT1();
        else                 CP_WAIT0();
        __syncthreads();
        if (it + 2 < ntiles) {
            const int nb = (buf + 2 >= 3) ? buf - 1 : buf + 2;
            LOADKV(nb, it + 2);
            CP_COMMIT();
        }
        const uint32_t kvb = sb0 + QREG + buf * SKV;

        if (it * 32 <= wrow_max) {
            float sS[4][4];
#pragma unroll
            for (int i = 0; i < 4; i++)
#pragma unroll
                for (int e = 0; e < 4; e++) sS[i][e] = 0.f;
#pragma unroll
            for (int kt = 0; kt < 8; kt++) {
                uint32_t kb[4][2];
#pragma unroll
                for (int p = 0; p < 2; p++) {
                    const uint32_t kaddr = kvb + (p * 16 + b_n) * AQS + kt * 32 + b_kb;
                    ldsm_x4(kb[2 * p][0], kb[2 * p][1],
                            kb[2 * p + 1][0], kb[2 * p + 1][1], kaddr);
                }
#pragma unroll
                for (int nt = 0; nt < 4; nt++) mma_f16(sS[nt], aQ[kt], kb[nt]);
            }

            const int kcol0 = it * 32 + 2 * t2;
            float ml0 = -1e30f, ml1 = -1e30f;
#pragma unroll
            for (int nt = 0; nt < 4; nt++) {
                const int c = kcol0 + nt * 8;
                float s0 = sS[nt][0] * sc2, s1 = sS[nt][1] * sc2;
                float s2 = sS[nt][2] * sc2, s3 = sS[nt][3] * sc2;
                if (c > qrow0)         s0 = -1e30f;
                if (c + 1 > qrow0)     s1 = -1e30f;
                if (c > qrow0 + 8)     s2 = -1e30f;
                if (c + 1 > qrow0 + 8) s3 = -1e30f;
                sS[nt][0] = s0; sS[nt][1] = s1; sS[nt][2] = s2; sS[nt][3] = s3;
                ml0 = fmaxf(ml0, fmaxf(s0, s1));
                ml1 = fmaxf(ml1, fmaxf(s2, s3));
            }
            ml0 = fmaxf(ml0, __shfl_xor_sync(0xffffffffu, ml0, 1));
            ml0 = fmaxf(ml0, __shfl_xor_sync(0xffffffffu, ml0, 2));
            ml1 = fmaxf(ml1, __shfl_xor_sync(0xffffffffu, ml1, 1));
            ml1 = fmaxf(ml1, __shfl_xor_sync(0xffffffffu, ml1, 2));
            const float mn0 = fmaxf(m0, ml0), mn1 = fmaxf(m1, ml1);
            const float al0 = ex2f(m0 - mn0), al1 = ex2f(m1 - mn1);

            float ps0 = 0.f, ps1 = 0.f;
            uint32_t aP[2][4];
#pragma unroll
            for (int u = 0; u < 2; u++) {
                const float p00 = ex2f(sS[2 * u][0] - mn0);
                const float p01 = ex2f(sS[2 * u][1] - mn0);
                const float p02 = ex2f(sS[2 * u][2] - mn1);
                const float p03 = ex2f(sS[2 * u][3] - mn1);
                const float p10 = ex2f(sS[2 * u + 1][0] - mn0);
                const float p11 = ex2f(sS[2 * u + 1][1] - mn0);
                const float p12 = ex2f(sS[2 * u + 1][2] - mn1);
                const float p13 = ex2f(sS[2 * u + 1][3] - mn1);
                ps0 += p00 + p01 + p10 + p11;
                ps1 += p02 + p03 + p12 + p13;
                aP[u][0] = spkh(p00, p01);
                aP[u][1] = spkh(p02, p03);
                aP[u][2] = spkh(p10, p11);
                aP[u][3] = spkh(p12, p13);
            }
            ps0 += __shfl_xor_sync(0xffffffffu, ps0, 1);
            ps0 += __shfl_xor_sync(0xffffffffu, ps0, 2);
            ps1 += __shfl_xor_sync(0xffffffffu, ps1, 1);
            ps1 += __shfl_xor_sync(0xffffffffu, ps1, 2);
            l0 = l0 * al0 + ps0;
            l1 = l1 * al1 + ps1;
            m0 = mn0; m1 = mn1;
#pragma unroll
            for (int i = 0; i < 16; i++) {
                O[i][0] *= al0; O[i][1] *= al0;
                O[i][2] *= al1; O[i][3] *= al1;
            }

#pragma unroll
            for (int u = 0; u < 2; u++) {
#pragma unroll
                for (int pp = 0; pp < 4; pp++) {
                    uint32_t vb[4][2];
#pragma unroll
                    for (int pi = 0; pi < 2; pi++) {
                        const int p = 2 * pp + pi;
                        const uint32_t vaddr =
                            kvb + 8704 + (p * 16 + b_n) * AVS + u * 32 + b_kb;
                        ldsm_x4(vb[2 * pi][0], vb[2 * pi][1],
                                vb[2 * pi + 1][0], vb[2 * pi + 1][1], vaddr);
                    }
#pragma unroll
                    for (int q = 0; q < 4; q++) mma_f16(O[4 * pp + q], aP[u], vb[q]);
                }
            }
        }
        buf = (buf == 2) ? 0 : buf + 1;
    }

    const float inv0 = 1.0f / l0, inv1 = 1.0f / l1;
    const size_t obase = (size_t)(b * TT + qrow0) * DM + h * DH;
#pragma unroll
    for (int ntd = 0; ntd < 16; ntd++) {
        const int d = ntd * 8 + 2 * t2;
        const float v0 = O[ntd][0] * inv0, v1 = O[ntd][1] * inv0;
        const float v2 = O[ntd][2] * inv1, v3 = O[ntd][3] * inv1;
        *(uint32_t*)&g_cf[obase + d] = spkh(v0, v1);
        *(uint32_t*)&g_cf[obase + 8 * DM + d] = spkh(v2, v3);
    }
}

// ============================================================
extern "C" void kernel_launch(void* const* d_in, const int* in_sizes, int n_in,
                              void* d_out, int out_size)
{
    const float* x  = (const float*)d_in[0];
    const float* Wq = (const float*)d_in[2];
    const float* bq = (const float*)d_in[3];
    const float* Wk = (const float*)d_in[4];
    const float* bk = (const float*)d_in[5];
    const float* Wv = (const float*)d_in[6];
    const float* bv = (const float*)d_in[7];
    const float* Wo = (const float*)d_in[8];
    const float* bo = (const float*)d_in[9];
    float* out = (float*)d_out;

    const int gsmem = 3 * STG;   // 61440
    cudaFuncSetAttribute(tc_gemm, cudaFuncAttributeMaxDynamicSharedMemorySize, gsmem);
    cudaFuncSetAttribute(attn_mma, cudaFuncAttributeMaxDynamicSharedMemorySize, ASMEM);

    prep_kernel<<<10752, 256>>>(x, Wq, Wk, Wv, Wo);

    tc_gemm<<<dim3(18, MROWS / 128), 128, gsmem>>>(bq, bk, bv, nullptr, 0);

    attn_mma<<<dim3(TT / 64, NH, BBAT), 128, ASMEM>>>();

    tc_gemm<<<dim3(16, MROWS / 128), 128, gsmem>>>(bo, nullptr, nullptr, out, 1);
}

// round 17
// speedup vs baseline: 2.5418x; 1.0508x over previous
#include <cuda_runtime.h>
#include <cuda_fp16.h>
#include <cstdint>

#define BBAT 4
#define TT 2048
#define DM 2048
#define NH 16
#define DH 128
#define MROWS (BBAT * TT)

// ---- scratch (single fp16 everywhere) ----
__device__ __half g_xf[(size_t)MROWS * DM];
__device__ __half g_cf[(size_t)MROWS * DM];
__device__ __half g_qf[(size_t)MROWS * DM];
__device__ __half g_k[(size_t)MROWS * DH];
__device__ __half g_vt[(size_t)DH * MROWS];
__device__ __half g_wq[(size_t)DM * DM];
__device__ __half g_wk[(size_t)DH * DM];
__device__ __half g_wv[(size_t)DH * DM];
__device__ __half g_wo[(size_t)DM * DM];

// ---- PTX helpers ----
__device__ __forceinline__ uint32_t smem_u32(const void* p) {
    uint32_t a;
    asm("{ .reg .u64 t; cvta.to.shared.u64 t, %1; cvt.u32.u64 %0, t; }" : "=r"(a) : "l"(p));
    return a;
}
#define CP16(s, g) \
    asm volatile("cp.async.cg.shared.global [%0], [%1], 16;" :: "r"(s), "l"(g))
#define CP_COMMIT() asm volatile("cp.async.commit_group;" ::: "memory")
#define CP_WAIT1() asm volatile("cp.async.wait_group 1;" ::: "memory")
#define CP_WAIT0() asm volatile("cp.async.wait_group 0;" ::: "memory")

__device__ __forceinline__ void ldsm_x4(uint32_t& r0, uint32_t& r1, uint32_t& r2,
                                        uint32_t& r3, uint32_t addr) {
    asm volatile("ldmatrix.sync.aligned.m8n8.x4.shared.b16 {%0,%1,%2,%3}, [%4];"
                 : "=r"(r0), "=r"(r1), "=r"(r2), "=r"(r3) : "r"(addr));
}
__device__ __forceinline__ void mma_f16(float* c, const uint32_t* a, const uint32_t* b) {
    asm volatile("mma.sync.aligned.m16n8k16.row.col.f32.f16.f16.f32 "
                 "{%0,%1,%2,%3}, {%4,%5,%6,%7}, {%8,%9}, {%0,%1,%2,%3};"
                 : "+f"(c[0]), "+f"(c[1]), "+f"(c[2]), "+f"(c[3])
                 : "r"(a[0]), "r"(a[1]), "r"(a[2]), "r"(a[3]), "r"(b[0]), "r"(b[1]));
}
__device__ __forceinline__ float ex2f(float x) {
    float y;
    asm("ex2.approx.f32 %0, %1;" : "=f"(y) : "f"(x));
    return y;
}
__device__ __forceinline__ uint32_t pk2h(__half a, __half b) {
    return (uint32_t)__half_as_ushort(a) | ((uint32_t)__half_as_ushort(b) << 16);
}
__device__ __forceinline__ uint32_t spkh(float a, float b) {
    return pk2h(__float2half_rn(a), __float2half_rn(b));
}

// ============================================================
// Fused prep (unchanged, validated)
// ============================================================
__device__ __forceinline__ void do_tsingle_h(const float* __restrict__ W,
                                             __half* dst, int Kd, int Nd, int bx2,
                                             float (*t)[33]) {
    const int xw = Nd / 32;
    const int nb = (bx2 % xw) * 32, kb = (bx2 / xw) * 32;
    const int tx = threadIdx.x & 31, ty = threadIdx.x >> 5;
#pragma unroll
    for (int i = 0; i < 4; i++)
        t[ty + 8 * i][tx] = W[(size_t)(kb + ty + 8 * i) * Nd + nb + tx];
    __syncthreads();
#pragma unroll
    for (int i = 0; i < 4; i++) {
        const int nrow = ty + 8 * i;
        dst[(size_t)(nb + nrow) * Kd + kb + tx] = __float2half_rn(t[tx][nrow]);
    }
}

__global__ __launch_bounds__(256) void prep_kernel(
    const float* __restrict__ x, const float* __restrict__ Wq,
    const float* __restrict__ Wk, const float* __restrict__ Wv,
    const float* __restrict__ Wo)
{
    __shared__ float t[32][33];
    const int bx = blockIdx.x;
    if (bx < 2048) {
        const int n4 = MROWS * DM / 4;
        for (int i = bx * 256 + threadIdx.x; i < n4; i += 2048 * 256) {
            float4 v = ((const float4*)x)[i];
            uint2 F;
            F.x = spkh(v.x, v.y);
            F.y = spkh(v.z, v.w);
            ((uint2*)g_xf)[i] = F;
        }
    } else if (bx < 6144) {
        do_tsingle_h(Wq, g_wq, DM, DM, bx - 2048, t);
    } else if (bx < 6400) {
        do_tsingle_h(Wk, g_wk, DM, DH, bx - 6144, t);
    } else if (bx < 6656) {
        do_tsingle_h(Wv, g_wv, DM, DH, bx - 6400, t);
    } else {
        do_tsingle_h(Wo, g_wo, DM, DM, bx - 6656, t);
    }
}

// ============================================================
// fp16 single-pass GEMM (validated R16, unchanged)
// ============================================================
#define STG 20480

__global__ __launch_bounds__(128, 2) void tc_gemm(
    const float* __restrict__ b0, const float* __restrict__ b1,
    const float* __restrict__ b2, float* __restrict__ Cext, int mode)
{
    extern __shared__ char sm[];
    const uint32_t sbase = smem_u32(sm);
    const int tid = threadIdx.x;
    const int lane = tid & 31, warp = tid >> 5;
    const int wm = warp & 1, wn = warp >> 1;
    const int bx = blockIdx.x;
    const int rowBase = blockIdx.y * 128;

    const __half* A = mode ? g_cf : g_xf;
    const __half* B;
    int wRow0;
    if (mode) { B = g_wo; wRow0 = bx * 128; }
    else if (bx < 16)  { B = g_wq; wRow0 = bx * 128; }
    else if (bx == 16) { B = g_wk; wRow0 = 0; }
    else               { B = g_wv; wRow0 = 0; }

    float acc[4][8][4];
#pragma unroll
    for (int mt = 0; mt < 4; mt++)
#pragma unroll
        for (int nt = 0; nt < 8; nt++)
#pragma unroll
            for (int e = 0; e < 4; e++) acc[mt][nt][e] = 0.f;

    const int lr = tid >> 2, lc = tid & 3;
    const int a_r = lane & 15;
    const uint32_t a_kb = (lane & 16) ? 16 : 0;
    const int b_n = (lane & 7) + ((lane & 16) ? 8 : 0);
    const uint32_t b_kb = (lane & 8) ? 16 : 0;
    const int g = lane >> 2, t2 = lane & 3;

#define LOAD_STAGE(buf, k0) do { \
    const uint32_t sb_ = sbase + (buf) * STG; \
    _Pragma("unroll") \
    for (int h_ = 0; h_ < 4; h_++) { \
        const int r_ = lr + h_ * 32; \
        const uint32_t so_ = r_ * 80 + lc * 16; \
        const size_t ga_ = (size_t)(rowBase + r_) * DM + (k0) + lc * 8; \
        const size_t gb_ = (size_t)(wRow0 + r_) * DM + (k0) + lc * 8; \
        CP16(sb_ + so_, A + ga_); \
        CP16(sb_ + 10240 + so_, B + gb_); \
    } \
} while (0)

    LOAD_STAGE(0, 0);
    CP_COMMIT();
    LOAD_STAGE(1, 32);
    CP_COMMIT();

    const int ITERS = DM / 32;
    int buf = 0;
    for (int s = 0; s < ITERS; s++) {
        if (s + 1 < ITERS) CP_WAIT1();
        else               CP_WAIT0();
        __syncthreads();
        if (s + 2 < ITERS) {
            const int nb = (buf + 2 >= 3) ? buf - 1 : buf + 2;
            LOAD_STAGE(nb, (s + 2) * 32);
            CP_COMMIT();
        }

        const uint32_t sb = sbase + buf * STG;
#pragma unroll
        for (int ks = 0; ks < 2; ks++) {
            const uint32_t kso = ks * 32;
            uint32_t ah[4][4], bb[8][2];
#pragma unroll
            for (int mt = 0; mt < 4; mt++) {
                const uint32_t addr = sb + (wm * 64 + mt * 16 + a_r) * 80 + kso + a_kb;
                ldsm_x4(ah[mt][0], ah[mt][1], ah[mt][2], ah[mt][3], addr);
            }
#pragma unroll
            for (int p = 0; p < 4; p++) {
                const uint32_t addr = sb + 10240 + (wn * 64 + p * 16 + b_n) * 80 + kso + b_kb;
                ldsm_x4(bb[p * 2][0], bb[p * 2][1], bb[p * 2 + 1][0], bb[p * 2 + 1][1], addr);
            }
#pragma unroll
            for (int mt = 0; mt < 4; mt++)
#pragma unroll
                for (int nt = 0; nt < 8; nt++)
                    mma_f16(acc[mt][nt], ah[mt], bb[nt]);
        }
        buf = (buf == 2) ? 0 : buf + 1;
    }

    if (mode) {
#pragma unroll
        for (int mt = 0; mt < 4; mt++) {
            const int r0 = rowBase + wm * 64 + mt * 16 + g;
#pragma unroll
            for (int nt = 0; nt < 8; nt++) {
                const int col = bx * 128 + wn * 64 + nt * 8 + t2 * 2;
                const float bxv = b0[col], byv = b0[col + 1];
                float2 o0, o1;
                o0.x = acc[mt][nt][0] + bxv; o0.y = acc[mt][nt][1] + byv;
                o1.x = acc[mt][nt][2] + bxv; o1.y = acc[mt][nt][3] + byv;
                *(float2*)(Cext + (size_t)r0 * DM + col) = o0;
                *(float2*)(Cext + (size_t)(r0 + 8) * DM + col) = o1;
            }
        }
    } else if (bx < 16) {
#pragma unroll
        for (int mt = 0; mt < 4; mt++) {
            const int r0 = rowBase + wm * 64 + mt * 16 + g;
#pragma unroll
            for (int nt = 0; nt < 8; nt++) {
                const int col = bx * 128 + wn * 64 + nt * 8 + t2 * 2;
                const float bxv = b0[col], byv = b0[col + 1];
                const float v0 = acc[mt][nt][0] + bxv, v1 = acc[mt][nt][1] + byv;
                const float v2 = acc[mt][nt][2] + bxv, v3 = acc[mt][nt][3] + byv;
                *(uint32_t*)&g_qf[(size_t)r0 * DM + col] = spkh(v0, v1);
                *(uint32_t*)&g_qf[(size_t)(r0 + 8) * DM + col] = spkh(v2, v3);
            }
        }
    } else if (bx == 16) {
#pragma unroll
        for (int mt = 0; mt < 4; mt++) {
            const int r0 = rowBase + wm * 64 + mt * 16 + g;
#pragma unroll
            for (int nt = 0; nt < 8; nt++) {
                const int col = wn * 64 + nt * 8 + t2 * 2;
                const float bxv = b1[col], byv = b1[col + 1];
                const float v0 = acc[mt][nt][0] + bxv, v1 = acc[mt][nt][1] + byv;
                const float v2 = acc[mt][nt][2] + bxv, v3 = acc[mt][nt][3] + byv;
                *(uint32_t*)&g_k[(size_t)r0 * DH + col] = spkh(v0, v1);
                *(uint32_t*)&g_k[(size_t)(r0 + 8) * DH + col] = spkh(v2, v3);
            }
        }
    } else {
#pragma unroll
        for (int mt = 0; mt < 4; mt++) {
            const int r0 = rowBase + wm * 64 + mt * 16 + g;
            const int bidx = r0 >> 11;
            const int trow = r0 & (TT - 1);
#pragma unroll
            for (int nt = 0; nt < 8; nt++) {
                const int col = wn * 64 + nt * 8 + t2 * 2;
                const float bxv = b2[col], byv = b2[col + 1];
                const float v0 = acc[mt][nt][0] + bxv, v1 = acc[mt][nt][1] + byv;
                const float v2 = acc[mt][nt][2] + bxv, v3 = acc[mt][nt][3] + byv;
                const size_t base0 = ((size_t)bidx * DH + col) * TT + trow;
                g_vt[base0]          = __float2half_rn(v0);
                g_vt[base0 + TT]     = __float2half_rn(v1);
                g_vt[base0 + 8]      = __float2half_rn(v2);
                g_vt[base0 + TT + 8] = __float2half_rn(v3);
            }
        }
    }
}

// ============================================================
// Flash attention fp16, BN=64 KV tiles (half the softmax/barrier
// overhead), 2-stage race-free pipeline, 2 CTAs/SM.
// smem: Q 0 (64x272=17408); stage s @ 17408+s*35840:
//   K +0 (64x272=17408), Vt +17408 (128x144=18432)
// ============================================================
#define AQS 272
#define AVS 144
#define QREG 17408
#define SKV 35840
#define ASMEM (QREG + 2 * SKV)   // 89088

__global__ __launch_bounds__(128, 2) void attn_mma()
{
    extern __shared__ char sm[];
    const uint32_t sb0 = smem_u32(sm);
    const int qt = gridDim.x - 1 - blockIdx.x;
    const int h = blockIdx.y, b = blockIdx.z;
    const int tid = threadIdx.x, lane = tid & 31, w = tid >> 5;
    const int g = lane >> 2, t2 = lane & 3;
    const int a_r = lane & 15;
    const uint32_t a_kb = (lane & 16) ? 16 : 0;
    const int b_n = (lane & 7) + ((lane & 16) ? 8 : 0);
    const uint32_t b_kb = (lane & 8) ? 16 : 0;

    {
        const size_t qbase = (size_t)(b * TT + qt * 64) * DM + h * DH;
#pragma unroll
        for (int j = 0; j < 8; j++) {
            const int n = tid + j * 128;
            const int row = n >> 4, ch = n & 15;
            CP16(sb0 + row * AQS + ch * 16, g_qf + qbase + (size_t)row * DM + ch * 8);
        }
    }
    CP_COMMIT();
    CP_WAIT0();
    __syncthreads();

    uint32_t aQ[8][4];
#pragma unroll
    for (int kt = 0; kt < 8; kt++) {
        const uint32_t qaddr = sb0 + (w * 16 + a_r) * AQS + kt * 32 + a_kb;
        ldsm_x4(aQ[kt][0], aQ[kt][1], aQ[kt][2], aQ[kt][3], qaddr);
    }

// BN=64 tile: K 64 rows x 128 d; Vt 128 d-rows x 64 t-cols
#define LOADKV(buf, kb) do { \
    const uint32_t kvb_ = sb0 + QREG + (buf) * SKV; \
    const size_t kbase_ = (size_t)(b * TT + (kb) * 64) * DH; \
    const size_t vbase_ = (size_t)b * DH * TT + (size_t)(kb) * 64; \
    _Pragma("unroll") \
    for (int j_ = 0; j_ < 8; j_++) { \
        const int n_ = tid + j_ * 128; \
        const int kr_ = n_ >> 4, kc_ = n_ & 15; \
        CP16(kvb_ + kr_ * AQS + kc_ * 16, g_k + kbase_ + (size_t)kr_ * DH + kc_ * 8); \
        const int vr_ = n_ >> 3, vc_ = n_ & 7; \
        CP16(kvb_ + QREG + vr_ * AVS + vc_ * 16, g_vt + vbase_ + (size_t)vr_ * TT + vc_ * 8); \
    } \
} while (0)

    const int ntiles = qt + 1;
    LOADKV(0, 0);
    CP_COMMIT();

    float O[16][4];
#pragma unroll
    for (int i = 0; i < 16; i++)
#pragma unroll
        for (int e = 0; e < 4; e++) O[i][e] = 0.f;
    float m0 = -1e30f, m1 = -1e30f, l0 = 0.f, l1 = 0.f;
    const float sc2 = 0.08838834764831845f * 1.4426950408889634f;
    const int qrow0 = qt * 64 + w * 16 + g;

    for (int it = 0; it < ntiles; it++) {
        CP_WAIT0();          // previous load complete
        __syncthreads();     // all warps done reading the other buffer
        if (it + 1 < ntiles) {
            LOADKV((it + 1) & 1, it + 1);
            CP_COMMIT();
        }
        const uint32_t kvb = sb0 + QREG + (it & 1) * SKV;

        // ---- S = Q K^T (single pass), 64 cols ----
        float sS[8][4];
#pragma unroll
        for (int i = 0; i < 8; i++)
#pragma unroll
            for (int e = 0; e < 4; e++) sS[i][e] = 0.f;
#pragma unroll
        for (int kt = 0; kt < 8; kt++) {
            uint32_t kb[8][2];
#pragma unroll
            for (int p = 0; p < 4; p++) {
                const uint32_t kaddr = kvb + (p * 16 + b_n) * AQS + kt * 32 + b_kb;
                ldsm_x4(kb[2 * p][0], kb[2 * p][1],
                        kb[2 * p + 1][0], kb[2 * p + 1][1], kaddr);
            }
#pragma unroll
            for (int nt = 0; nt < 8; nt++) mma_f16(sS[nt], aQ[kt], kb[nt]);
        }

        // ---- online softmax (log2 domain) ----
        const int kcol0 = it * 64 + 2 * t2;
        float ml0 = -1e30f, ml1 = -1e30f;
#pragma unroll
        for (int nt = 0; nt < 8; nt++) {
            const int c = kcol0 + nt * 8;
            float s0 = sS[nt][0] * sc2, s1 = sS[nt][1] * sc2;
            float s2 = sS[nt][2] * sc2, s3 = sS[nt][3] * sc2;
            if (c > qrow0)         s0 = -1e30f;
            if (c + 1 > qrow0)     s1 = -1e30f;
            if (c > qrow0 + 8)     s2 = -1e30f;
            if (c + 1 > qrow0 + 8) s3 = -1e30f;
            sS[nt][0] = s0; sS[nt][1] = s1; sS[nt][2] = s2; sS[nt][3] = s3;
            ml0 = fmaxf(ml0, fmaxf(s0, s1));
            ml1 = fmaxf(ml1, fmaxf(s2, s3));
        }
        ml0 = fmaxf(ml0, __shfl_xor_sync(0xffffffffu, ml0, 1));
        ml0 = fmaxf(ml0, __shfl_xor_sync(0xffffffffu, ml0, 2));
        ml1 = fmaxf(ml1, __shfl_xor_sync(0xffffffffu, ml1, 1));
        ml1 = fmaxf(ml1, __shfl_xor_sync(0xffffffffu, ml1, 2));
        const float mn0 = fmaxf(m0, ml0), mn1 = fmaxf(m1, ml1);
        const float al0 = ex2f(m0 - mn0), al1 = ex2f(m1 - mn1);

        float ps0 = 0.f, ps1 = 0.f;
        uint32_t aP[4][4];
#pragma unroll
        for (int u = 0; u < 4; u++) {
            const float p00 = ex2f(sS[2 * u][0] - mn0);
            const float p01 = ex2f(sS[2 * u][1] - mn0);
            const float p02 = ex2f(sS[2 * u][2] - mn1);
            const float p03 = ex2f(sS[2 * u][3] - mn1);
            const float p10 = ex2f(sS[2 * u + 1][0] - mn0);
            const float p11 = ex2f(sS[2 * u + 1][1] - mn0);
            const float p12 = ex2f(sS[2 * u + 1][2] - mn1);
            const float p13 = ex2f(sS[2 * u + 1][3] - mn1);
            ps0 += p00 + p01 + p10 + p11;
            ps1 += p02 + p03 + p12 + p13;
            aP[u][0] = spkh(p00, p01);
            aP[u][1] = spkh(p02, p03);
            aP[u][2] = spkh(p10, p11);
            aP[u][3] = spkh(p12, p13);
        }
        ps0 += __shfl_xor_sync(0xffffffffu, ps0, 1);
        ps0 += __shfl_xor_sync(0xffffffffu, ps0, 2);
        ps1 += __shfl_xor_sync(0xffffffffu, ps1, 1);
        ps1 += __shfl_xor_sync(0xffffffffu, ps1, 2);
        l0 = l0 * al0 + ps0;
        l1 = l1 * al1 + ps1;
        m0 = mn0; m1 = mn1;
#pragma unroll
        for (int i = 0; i < 16; i++) {
            O[i][0] *= al0; O[i][1] *= al0;
            O[i][2] *= al1; O[i][3] *= al1;
        }

        // ---- O += P V (single pass), k-dim 64 ----
#pragma unroll
        for (int u = 0; u < 4; u++) {
#pragma unroll
            for (int pp = 0; pp < 4; pp++) {
                uint32_t vb[4][2];
#pragma unroll
                for (int pi = 0; pi < 2; pi++) {
                    const int p = 2 * pp + pi;
                    const uint32_t vaddr =
                        kvb + QREG + (p * 16 + b_n) * AVS + u * 32 + b_kb;
                    ldsm_x4(vb[2 * pi][0], vb[2 * pi][1],
                            vb[2 * pi + 1][0], vb[2 * pi + 1][1], vaddr);
                }
#pragma unroll
                for (int q = 0; q < 4; q++) mma_f16(O[4 * pp + q], aP[u], vb[q]);
            }
        }
    }

    const float inv0 = 1.0f / l0, inv1 = 1.0f / l1;
    const size_t obase = (size_t)(b * TT + qrow0) * DM + h * DH;
#pragma unroll
    for (int ntd = 0; ntd < 16; ntd++) {
        const int d = ntd * 8 + 2 * t2;
        const float v0 = O[ntd][0] * inv0, v1 = O[ntd][1] * inv0;
        const float v2 = O[ntd][2] * inv1, v3 = O[ntd][3] * inv1;
        *(uint32_t*)&g_cf[obase + d] = spkh(v0, v1);
        *(uint32_t*)&g_cf[obase + 8 * DM + d] = spkh(v2, v3);
    }
}

// ============================================================
extern "C" void kernel_launch(void* const* d_in, const int* in_sizes, int n_in,
                              void* d_out, int out_size)
{
    const float* x  = (const float*)d_in[0];
    const float* Wq = (const float*)d_in[2];
    const float* bq = (const float*)d_in[3];
    const float* Wk = (const float*)d_in[4];
    const float* bk = (const float*)d_in[5];
    const float* Wv = (const float*)d_in[6];
    const float* bv = (const float*)d_in[7];
    const float* Wo = (const float*)d_in[8];
    const float* bo = (const float*)d_in[9];
    float* out = (float*)d_out;

    const int gsmem = 3 * STG;
    cudaFuncSetAttribute(tc_gemm, cudaFuncAttributeMaxDynamicSharedMemorySize, gsmem);
    cudaFuncSetAttribute(attn_mma, cudaFuncAttributeMaxDynamicSharedMemorySize, ASMEM);

    prep_kernel<<<10752, 256>>>(x, Wq, Wk, Wv, Wo);

    tc_gemm<<<dim3(18, MROWS / 128), 128, gsmem>>>(bq, bk, bv, nullptr, 0);

    attn_mma<<<dim3(TT / 64, NH, BBAT), 128, ASMEM>>>();

    tc_gemm<<<dim3(16, MROWS / 128), 128, gsmem>>>(bo, nullptr, nullptr, out, 1);
}